// round 10
// baseline (speedup 1.0000x reference)
#include <cuda_runtime.h>
#include <cuda_fp16.h>
#include <math.h>
#include <stdint.h>

#define N_TOK 8192
#define DIM   512
#define GN_EPS 1e-5f

// ---------------- scratch (static device arrays; runtime alloc is forbidden) ----------------
__device__ __half g_Q [(size_t)N_TOK * DIM];
__device__ __half g_K [(size_t)N_TOK * DIM];
__device__ __half g_Vt[(size_t)N_TOK * DIM];         // V transposed [DIM][N_TOK]
__device__ __half g_S [(size_t)N_TOK * N_TOK];       // 128 MB retention matrix (fp16)
__device__ __half g_X [(size_t)N_TOK * DIM];
__device__ __half g_H [(size_t)N_TOK * DIM];
__device__ __half g_xh[(size_t)N_TOK * DIM];         // fp16 x
__device__ __half g_Wt[5 * (size_t)DIM * DIM];       // transposed fp16 weights

// ---------------- helpers ----------------
__device__ __forceinline__ uint32_t smem_u32(const void* p) {
    return (uint32_t)__cvta_generic_to_shared(p);
}
__device__ __forceinline__ void cpasync16(uint32_t dst, const void* src) {
    asm volatile("cp.async.cg.shared.global [%0], [%1], 16;" :: "r"(dst), "l"(src));
}
__device__ __forceinline__ void ldmatrix_x4(uint32_t& r0, uint32_t& r1, uint32_t& r2, uint32_t& r3,
                                            uint32_t addr) {
    asm volatile("ldmatrix.sync.aligned.m8n8.x4.shared.b16 {%0,%1,%2,%3}, [%4];"
                 : "=r"(r0), "=r"(r1), "=r"(r2), "=r"(r3) : "r"(addr));
}
__device__ __forceinline__ void mma_f16(float* c, const uint32_t* a, const uint32_t* b) {
    asm volatile("mma.sync.aligned.m16n8k16.row.col.f32.f16.f16.f32 "
                 "{%0,%1,%2,%3}, {%4,%5,%6,%7}, {%8,%9}, {%0,%1,%2,%3};"
                 : "+f"(c[0]), "+f"(c[1]), "+f"(c[2]), "+f"(c[3])
                 : "r"(a[0]), "r"(a[1]), "r"(a[2]), "r"(a[3]), "r"(b[0]), "r"(b[1]));
}

// ---------------- fp16 NT tensor-core GEMM ----------------
// C[M,Nn] = A[M,Kk] @ B^T, A/B are __half [.][Kk] row-major, fp32 accumulate.
// Block 128x128, 8 warps (2 M x 4 N), warp tile 64x32, BK=64 (128B rows, SW128 swizzle),
// 3-stage cp.async pipeline, 2 CTAs/SM.
// EPI: 0 = +bias[col] (may be null), 1 = gelu(c+bias[col]),
//      2 = c * Dm[row,col] (streaming loads/stores, evict-first),
//      3 = +bias[row], 4 = bias[col] then fused GroupNorm (gamma/beta), fp32 out
// BATCH2: grid.z==1 selects {B2, bias2, C2}
template<int EPI, bool BATCH2, typename OutT>
__global__ __launch_bounds__(256, 2)
void gemm_h(const __half* __restrict__ A, const __half* __restrict__ Bp,
            const float* __restrict__ biasp, const float* __restrict__ Dm,
            const float* __restrict__ gm, const float* __restrict__ bt,
            OutT* __restrict__ Cp, int M, int Nn, int Kk,
            const __half* __restrict__ B2, const float* __restrict__ bias2,
            OutT* __restrict__ C2)
{
    constexpr int BM = 128, BN = 128, BK = 64, STAGES = 3;
    constexpr int A_BYTES = BM * BK * 2;          // 16384
    constexpr int B_BYTES = BN * BK * 2;          // 16384
    constexpr int STG_BYTES = A_BYTES + B_BYTES;  // 32768
    extern __shared__ char smem[];
    const uint32_t sbase = smem_u32(smem);

    const __half* B    = Bp;
    const float*  bias = biasp;
    OutT*         C    = Cp;
    if (BATCH2 && blockIdx.z == 1) { B = B2; bias = bias2; C = C2; }

    const int t    = threadIdx.x;
    const int lane = t & 31;
    const int wid  = t >> 5;
    const int wm   = (wid & 1) * 64;              // 2 warps along M
    const int wn   = (wid >> 1) * 32;             // 4 warps along N
    const int br   = blockIdx.y;
    const int bc   = blockIdx.x;

    const int lr = t >> 3;                        // 0..31 (+32 per pass)
    const int lu = t & 7;                         // 16B unit in 128B row

    float acc[4][4][4];
    #pragma unroll
    for (int i = 0; i < 4; i++)
        #pragma unroll
        for (int j = 0; j < 4; j++)
            #pragma unroll
            for (int q = 0; q < 4; q++) acc[i][j][q] = 0.f;

    auto load_stage = [&](int it) {
        const uint32_t ab = sbase + (it % STAGES) * STG_BYTES;
        const uint32_t bb = ab + A_BYTES;
        const __half* Ag = A + (size_t)(br * BM) * Kk + it * BK;
        const __half* Bg = B + (size_t)(bc * BN) * Kk + it * BK;
        #pragma unroll
        for (int p = 0; p < 4; p++) {
            const int r = lr + p * 32;
            cpasync16(ab + r * 128 + ((lu ^ (r & 7)) << 4), Ag + (size_t)r * Kk + lu * 8);
        }
        #pragma unroll
        for (int p = 0; p < 4; p++) {
            const int r = lr + p * 32;
            cpasync16(bb + r * 128 + ((lu ^ (r & 7)) << 4), Bg + (size_t)r * Kk + lu * 8);
        }
        asm volatile("cp.async.commit_group;" ::: "memory");
    };

    auto compute_stage = [&](int it) {
        const uint32_t ab = sbase + (it % STAGES) * STG_BYTES;
        const uint32_t bb = ab + A_BYTES;
        const int j  = lane >> 3;                 // 0..3
        const int rr = lane & 7;
        #pragma unroll
        for (int ks = 0; ks < 4; ks++) {          // 4 x k16 steps = BK=64
            const int ub = ks * 2;                // base 16B-unit
            uint32_t af[4][4];
            #pragma unroll
            for (int mf = 0; mf < 4; mf++) {
                const int row  = wm + mf * 16 + (j & 1) * 8 + rr;
                const int unit = ub + (j >> 1);
                ldmatrix_x4(af[mf][0], af[mf][1], af[mf][2], af[mf][3],
                            ab + row * 128 + ((unit ^ (row & 7)) << 4));
            }
            uint32_t bf[4][2];
            #pragma unroll
            for (int nb = 0; nb < 2; nb++) {
                const int row  = wn + nb * 16 + (j >> 1) * 8 + rr;
                const int unit = ub + (j & 1);
                uint32_t r0, r1, r2, r3;
                ldmatrix_x4(r0, r1, r2, r3, bb + row * 128 + ((unit ^ (row & 7)) << 4));
                bf[nb * 2 + 0][0] = r0; bf[nb * 2 + 0][1] = r1;
                bf[nb * 2 + 1][0] = r2; bf[nb * 2 + 1][1] = r3;
            }
            #pragma unroll
            for (int mf = 0; mf < 4; mf++)
                #pragma unroll
                for (int nf = 0; nf < 4; nf++)
                    mma_f16(acc[mf][nf], af[mf], bf[nf]);
        }
    };

    const int nk = Kk / BK;
    load_stage(0);
    load_stage(1);
    for (int it = 0; it < nk; it++) {
        if (it + 1 < nk) asm volatile("cp.async.wait_group 1;" ::: "memory");
        else             asm volatile("cp.async.wait_group 0;" ::: "memory");
        __syncthreads();
        if (it + 2 < nk) load_stage(it + 2);
        compute_stage(it);
    }

    // ---- epilogue ----
    const int g = lane >> 2, tg = lane & 3;

    if (EPI == 4) {
        // bias[col] + fused GroupNorm. Warp covers 32 cols == exactly one group.
        #pragma unroll
        for (int mf = 0; mf < 4; mf++) {
            #pragma unroll
            for (int h = 0; h < 2; h++) {
                const int row = br * BM + wm + mf * 16 + g + h * 8;
                float v[8];
                #pragma unroll
                for (int nf = 0; nf < 4; nf++) {
                    const int col = bc * BN + wn + nf * 8 + tg * 2;
                    v[nf * 2 + 0] = acc[mf][nf][h * 2 + 0] + bias[col];
                    v[nf * 2 + 1] = acc[mf][nf][h * 2 + 1] + bias[col + 1];
                }
                float s = 0.f, s2 = 0.f;
                #pragma unroll
                for (int q = 0; q < 8; q++) { s += v[q]; s2 += v[q] * v[q]; }
                s  += __shfl_xor_sync(0xffffffffu, s, 1);
                s  += __shfl_xor_sync(0xffffffffu, s, 2);
                s2 += __shfl_xor_sync(0xffffffffu, s2, 1);
                s2 += __shfl_xor_sync(0xffffffffu, s2, 2);
                const float mu  = s * (1.f / 32.f);
                const float var = s2 * (1.f / 32.f) - mu * mu;
                const float inv = rsqrtf(var + GN_EPS);
                #pragma unroll
                for (int nf = 0; nf < 4; nf++) {
                    const int col = bc * BN + wn + nf * 8 + tg * 2;
                    float c0 = (v[nf * 2 + 0] - mu) * inv * gm[col]     + bt[col];
                    float c1 = (v[nf * 2 + 1] - mu) * inv * gm[col + 1] + bt[col + 1];
                    float2 o = { c0, c1 };
                    *(float2*)((float*)C + (size_t)row * Nn + col) = o;
                }
            }
        }
        return;
    }

    #pragma unroll
    for (int mf = 0; mf < 4; mf++) {
        #pragma unroll
        for (int nf = 0; nf < 4; nf++) {
            const int col = bc * BN + wn + nf * 8 + tg * 2;
            #pragma unroll
            for (int h = 0; h < 2; h++) {
                const int row = br * BM + wm + mf * 16 + g + h * 8;
                float c0 = acc[mf][nf][h * 2 + 0];
                float c1 = acc[mf][nf][h * 2 + 1];
                if (EPI == 2) {
                    // streaming (evict-first) D load: read exactly once, keep Q/K in L2
                    float dx, dy;
                    const float* dp = Dm + (size_t)row * Nn + col;
                    asm volatile("ld.global.cs.v2.f32 {%0,%1}, [%2];"
                                 : "=f"(dx), "=f"(dy) : "l"(dp));
                    c0 *= dx; c1 *= dy;
                } else if (EPI == 3) {
                    const float b = bias[row];
                    c0 += b; c1 += b;
                } else {
                    if (bias) { c0 += bias[col]; c1 += bias[col + 1]; }
                    if (EPI == 1) {
                        c0 = 0.5f * c0 * (1.f + erff(c0 * 0.70710678118654752f));
                        c1 = 0.5f * c1 * (1.f + erff(c1 * 0.70710678118654752f));
                    }
                }
                OutT* Cq = C + (size_t)row * Nn + col;
                if (sizeof(OutT) == 2) {
                    __half2 o = __floats2half2_rn(c0, c1);
                    if (EPI == 2) {
                        // streaming S store: written once, read once later
                        asm volatile("st.global.cs.u32 [%0], %1;"
                                     :: "l"(Cq), "r"(*(uint32_t*)&o) : "memory");
                    } else {
                        *(__half2*)Cq = o;
                    }
                } else {
                    float2 o = { c0, c1 };
                    *(float2*)Cq = o;
                }
            }
        }
    }
}

// ---------------- fused prep: 5 weight transposes (fp32->fp16) + x fp32->fp16 ----------------
__global__ void prep_k(const float* __restrict__ Wq, const float* __restrict__ Wk,
                       const float* __restrict__ Wv, const float* __restrict__ Wf,
                       const float* __restrict__ Wp, const float* __restrict__ x,
                       __half* __restrict__ Wt, __half* __restrict__ xh)
{
    const int b = blockIdx.x;
    const int t = threadIdx.x;
    if (b < 1280) {
        __shared__ float tile[32][33];
        const int w  = b >> 8;                   // weight index 0..4
        const int ti = b & 255;
        const int bx = ti & 15, by = ti >> 4;
        const float* in = (w == 0) ? Wq : (w == 1) ? Wk : (w == 2) ? Wv : (w == 3) ? Wf : Wp;
        __half* out = Wt + (size_t)w * DIM * DIM;
        const int tx = t & 31, tyb = t >> 5;     // 32 x 8
        int x0 = bx * 32 + tx;
        #pragma unroll
        for (int i = 0; i < 32; i += 8)
            tile[tyb + i][tx] = in[(size_t)(by * 32 + tyb + i) * DIM + x0];
        __syncthreads();
        int x1 = by * 32 + tx;
        #pragma unroll
        for (int i = 0; i < 32; i += 8)
            out[(size_t)(bx * 32 + tyb + i) * DIM + x1] = __float2half_rn(tile[tx][tyb + i]);
    } else {
        const int i = (b - 1280) * 256 + t;      // < 1048576
        float4 v = ((const float4*)x)[i];
        __half2 a = __floats2half2_rn(v.x, v.y);
        __half2 c = __floats2half2_rn(v.z, v.w);
        uint2 o = { *(uint32_t*)&a, *(uint32_t*)&c };
        ((uint2*)xh)[i] = o;
    }
}

// ---------------- launch ----------------
extern "C" void kernel_launch(void* const* d_in, const int* in_sizes, int n_in,
                              void* d_out, int out_size)
{
    const float* x     = (const float*)d_in[0];
    const float* D     = (const float*)d_in[1];
    const float* Wq    = (const float*)d_in[2];
    const float* bq    = (const float*)d_in[3];
    const float* Wk    = (const float*)d_in[4];
    const float* bk    = (const float*)d_in[5];
    const float* Wv    = (const float*)d_in[6];
    const float* bv    = (const float*)d_in[7];
    const float* Wf    = (const float*)d_in[8];
    const float* bf    = (const float*)d_in[9];
    const float* Wp    = (const float*)d_in[10];
    const float* bp    = (const float*)d_in[11];
    const float* gamma = (const float*)d_in[12];
    const float* beta  = (const float*)d_in[13];
    float* out = (float*)d_out;

    __half *Q, *K, *Vt, *S, *X, *H, *xh, *Wt;
    cudaGetSymbolAddress((void**)&Q,  g_Q);
    cudaGetSymbolAddress((void**)&K,  g_K);
    cudaGetSymbolAddress((void**)&Vt, g_Vt);
    cudaGetSymbolAddress((void**)&S,  g_S);
    cudaGetSymbolAddress((void**)&X,  g_X);
    cudaGetSymbolAddress((void**)&H,  g_H);
    cudaGetSymbolAddress((void**)&xh, g_xh);
    cudaGetSymbolAddress((void**)&Wt, g_Wt);

    __half* Wqt = Wt + 0 * (size_t)DIM * DIM;
    __half* Wkt = Wt + 1 * (size_t)DIM * DIM;
    __half* Wvt = Wt + 2 * (size_t)DIM * DIM;
    __half* Wft = Wt + 3 * (size_t)DIM * DIM;
    __half* Wpt = Wt + 4 * (size_t)DIM * DIM;

    const int SMEM = 3 * (128 + 128) * 64 * 2;   // 98304 B
    cudaFuncSetAttribute(gemm_h<0, true,  __half>, cudaFuncAttributeMaxDynamicSharedMemorySize, SMEM);
    cudaFuncSetAttribute(gemm_h<0, false, __half>, cudaFuncAttributeMaxDynamicSharedMemorySize, SMEM);
    cudaFuncSetAttribute(gemm_h<1, false, __half>, cudaFuncAttributeMaxDynamicSharedMemorySize, SMEM);
    cudaFuncSetAttribute(gemm_h<2, false, __half>, cudaFuncAttributeMaxDynamicSharedMemorySize, SMEM);
    cudaFuncSetAttribute(gemm_h<3, false, __half>, cudaFuncAttributeMaxDynamicSharedMemorySize, SMEM);
    cudaFuncSetAttribute(gemm_h<4, false, float>,  cudaFuncAttributeMaxDynamicSharedMemorySize, SMEM);

    dim3 blk(256);
    dim3 g_thin(DIM / 128, N_TOK / 128);         // 4 x 64 = 256
    dim3 g_qk  (DIM / 128, N_TOK / 128, 2);      // 512 (Q and K batched)
    dim3 g_fat (N_TOK / 128, N_TOK / 128);       // 64 x 64 = 4096
    dim3 g_vt  (N_TOK / 128, DIM / 128);         // 64 x 4  = 256

    // 1. prep: weight transposes + x conversion
    prep_k<<<5376, 256>>>(Wq, Wk, Wv, Wf, Wp, x, Wt, xh);
    // 2. Vt[d][n] = Wv^T row d . x row n + bv[d]  (row-bias)
    gemm_h<3, false, __half><<<g_vt, blk, SMEM>>>(Wvt, xh, bv, nullptr, nullptr, nullptr,
                                                  Vt, DIM, N_TOK, DIM, nullptr, nullptr, nullptr);
    // 3. Q and K projections batched over grid.z
    gemm_h<0, true, __half><<<g_qk, blk, SMEM>>>(xh, Wqt, bq, nullptr, nullptr, nullptr,
                                                 Q, N_TOK, DIM, DIM, Wkt, bk, K);
    // 4. S = fp16( D .* (Q @ K^T) )  streaming D/S epilogue
    gemm_h<2, false, __half><<<g_fat, blk, SMEM>>>(Q, K, nullptr, D, nullptr, nullptr,
                                                   S, N_TOK, N_TOK, DIM, nullptr, nullptr, nullptr);
    // 5. X = fp16( S @ V ) = S @ Vt^T
    gemm_h<0, false, __half><<<g_thin, blk, SMEM>>>(S, Vt, nullptr, nullptr, nullptr, nullptr,
                                                    X, N_TOK, DIM, N_TOK, nullptr, nullptr, nullptr);
    // 6. H = fp16( gelu(X @ Wf + bf) )
    gemm_h<1, false, __half><<<g_thin, blk, SMEM>>>(X, Wft, bf, nullptr, nullptr, nullptr,
                                                    H, N_TOK, DIM, DIM, nullptr, nullptr, nullptr);
    // 7. out = GroupNorm(H @ Wp + bp) fused
    gemm_h<4, false, float><<<g_thin, blk, SMEM>>>(H, Wpt, bp, nullptr, gamma, beta,
                                                   out, N_TOK, DIM, DIM, nullptr, nullptr, nullptr);
}

// round 11
// speedup vs baseline: 1.1540x; 1.1540x over previous
#include <cuda_runtime.h>
#include <cuda_fp16.h>
#include <math.h>
#include <stdint.h>

#define N_TOK 8192
#define DIM   512
#define GN_EPS 1e-5f

// ---------------- scratch (static device arrays; runtime alloc is forbidden) ----------------
__device__ __half g_Q [(size_t)N_TOK * DIM];
__device__ __half g_K [(size_t)N_TOK * DIM];
__device__ __half g_Vt[(size_t)N_TOK * DIM];         // V transposed [DIM][N_TOK]
__device__ __half g_S [(size_t)N_TOK * N_TOK];       // 128 MB retention matrix (fp16)
__device__ __half g_X [(size_t)N_TOK * DIM];
__device__ __half g_H [(size_t)N_TOK * DIM];
__device__ __half g_xh[(size_t)N_TOK * DIM];         // fp16 x
__device__ __half g_Wt[5 * (size_t)DIM * DIM];       // transposed fp16 weights

// ---------------- helpers ----------------
__device__ __forceinline__ uint32_t smem_u32(const void* p) {
    return (uint32_t)__cvta_generic_to_shared(p);
}
__device__ __forceinline__ void cpasync16(uint32_t dst, const void* src) {
    asm volatile("cp.async.cg.shared.global [%0], [%1], 16;" :: "r"(dst), "l"(src));
}
__device__ __forceinline__ void ldmatrix_x4(uint32_t& r0, uint32_t& r1, uint32_t& r2, uint32_t& r3,
                                            uint32_t addr) {
    asm volatile("ldmatrix.sync.aligned.m8n8.x4.shared.b16 {%0,%1,%2,%3}, [%4];"
                 : "=r"(r0), "=r"(r1), "=r"(r2), "=r"(r3) : "r"(addr));
}
__device__ __forceinline__ void mma_f16(float* c, const uint32_t* a, const uint32_t* b) {
    asm volatile("mma.sync.aligned.m16n8k16.row.col.f32.f16.f16.f32 "
                 "{%0,%1,%2,%3}, {%4,%5,%6,%7}, {%8,%9}, {%0,%1,%2,%3};"
                 : "+f"(c[0]), "+f"(c[1]), "+f"(c[2]), "+f"(c[3])
                 : "r"(a[0]), "r"(a[1]), "r"(a[2]), "r"(a[3]), "r"(b[0]), "r"(b[1]));
}

// ---------------- fp16 NT tensor-core GEMM ----------------
// C[M,Nn] = A[M,Kk] @ B^T, A/B are __half [.][Kk] row-major, fp32 accumulate.
// Block 128x128, 4 warps (2 M x 2 N), warp tile 64x64, BK=64 (128B rows, SW128 swizzle),
// 3-stage cp.async pipeline, 2 CTAs/SM (128 threads, ~190 regs).
// EPI: 0 = +bias[col] (may be null), 1 = gelu(c+bias[col]), 2 = c * Dm[row,col],
//      3 = +bias[row], 4 = bias[col] then fused GroupNorm (gamma/beta), fp32 out
// BATCH2: grid.z==1 selects {B2, bias2, C2}
template<int EPI, bool BATCH2, typename OutT>
__global__ __launch_bounds__(128, 2)
void gemm_h(const __half* __restrict__ A, const __half* __restrict__ Bp,
            const float* __restrict__ biasp, const float* __restrict__ Dm,
            const float* __restrict__ gm, const float* __restrict__ bt,
            OutT* __restrict__ Cp, int M, int Nn, int Kk,
            const __half* __restrict__ B2, const float* __restrict__ bias2,
            OutT* __restrict__ C2)
{
    constexpr int BM = 128, BN = 128, BK = 64, STAGES = 3;
    constexpr int A_BYTES = BM * BK * 2;          // 16384
    constexpr int B_BYTES = BN * BK * 2;          // 16384
    constexpr int STG_BYTES = A_BYTES + B_BYTES;  // 32768
    extern __shared__ char smem[];
    const uint32_t sbase = smem_u32(smem);

    const __half* B    = Bp;
    const float*  bias = biasp;
    OutT*         C    = Cp;
    if (BATCH2 && blockIdx.z == 1) { B = B2; bias = bias2; C = C2; }

    const int t    = threadIdx.x;
    const int lane = t & 31;
    const int wid  = t >> 5;                      // 0..3
    const int wm   = (wid & 1) * 64;              // 2 warps along M
    const int wn   = (wid >> 1) * 64;             // 2 warps along N
    const int br   = blockIdx.y;
    const int bc   = blockIdx.x;

    const int lr = t >> 3;                        // 0..15 (+16 per pass)
    const int lu = t & 7;                         // 16B unit in 128B row

    float acc[4][8][4];
    #pragma unroll
    for (int i = 0; i < 4; i++)
        #pragma unroll
        for (int j = 0; j < 8; j++)
            #pragma unroll
            for (int q = 0; q < 4; q++) acc[i][j][q] = 0.f;

    auto load_stage = [&](int it) {
        const uint32_t ab = sbase + (it % STAGES) * STG_BYTES;
        const uint32_t bb = ab + A_BYTES;
        const __half* Ag = A + (size_t)(br * BM) * Kk + it * BK;
        const __half* Bg = B + (size_t)(bc * BN) * Kk + it * BK;
        #pragma unroll
        for (int p = 0; p < 8; p++) {
            const int r = lr + p * 16;
            cpasync16(ab + r * 128 + ((lu ^ (r & 7)) << 4), Ag + (size_t)r * Kk + lu * 8);
        }
        #pragma unroll
        for (int p = 0; p < 8; p++) {
            const int r = lr + p * 16;
            cpasync16(bb + r * 128 + ((lu ^ (r & 7)) << 4), Bg + (size_t)r * Kk + lu * 8);
        }
        asm volatile("cp.async.commit_group;" ::: "memory");
    };

    auto compute_stage = [&](int it) {
        const uint32_t ab = sbase + (it % STAGES) * STG_BYTES;
        const uint32_t bb = ab + A_BYTES;
        const int j  = lane >> 3;                 // 0..3
        const int rr = lane & 7;
        #pragma unroll
        for (int ks = 0; ks < 4; ks++) {          // 4 x k16 steps = BK=64
            const int ub = ks * 2;                // base 16B-unit
            uint32_t af[4][4];
            #pragma unroll
            for (int mf = 0; mf < 4; mf++) {
                const int row  = wm + mf * 16 + (j & 1) * 8 + rr;
                const int unit = ub + (j >> 1);
                ldmatrix_x4(af[mf][0], af[mf][1], af[mf][2], af[mf][3],
                            ab + row * 128 + ((unit ^ (row & 7)) << 4));
            }
            uint32_t bf[8][2];
            #pragma unroll
            for (int nb = 0; nb < 4; nb++) {
                const int row  = wn + nb * 16 + (j >> 1) * 8 + rr;
                const int unit = ub + (j & 1);
                uint32_t r0, r1, r2, r3;
                ldmatrix_x4(r0, r1, r2, r3, bb + row * 128 + ((unit ^ (row & 7)) << 4));
                bf[nb * 2 + 0][0] = r0; bf[nb * 2 + 0][1] = r1;
                bf[nb * 2 + 1][0] = r2; bf[nb * 2 + 1][1] = r3;
            }
            #pragma unroll
            for (int mf = 0; mf < 4; mf++)
                #pragma unroll
                for (int nf = 0; nf < 8; nf++)
                    mma_f16(acc[mf][nf], af[mf], bf[nf]);
        }
    };

    const int nk = Kk / BK;
    load_stage(0);
    load_stage(1);
    for (int it = 0; it < nk; it++) {
        if (it + 1 < nk) asm volatile("cp.async.wait_group 1;" ::: "memory");
        else             asm volatile("cp.async.wait_group 0;" ::: "memory");
        __syncthreads();
        if (it + 2 < nk) load_stage(it + 2);
        compute_stage(it);
    }

    // ---- epilogue ----
    const int g = lane >> 2, tg = lane & 3;

    if (EPI == 4) {
        // bias[col] + fused GroupNorm. Warp covers 64 cols == two 32-channel groups;
        // per row each group's 32 values live in the 4 lanes sharing g (tg=0..3).
        #pragma unroll
        for (int mf = 0; mf < 4; mf++) {
            #pragma unroll
            for (int h = 0; h < 2; h++) {
                const int row = br * BM + wm + mf * 16 + g + h * 8;
                float v[16];
                #pragma unroll
                for (int nf = 0; nf < 8; nf++) {
                    const int col = bc * BN + wn + nf * 8 + tg * 2;
                    v[nf * 2 + 0] = acc[mf][nf][h * 2 + 0] + bias[col];
                    v[nf * 2 + 1] = acc[mf][nf][h * 2 + 1] + bias[col + 1];
                }
                #pragma unroll
                for (int grp = 0; grp < 2; grp++) {
                    float s = 0.f, s2 = 0.f;
                    #pragma unroll
                    for (int q = 0; q < 8; q++) {
                        const float z = v[grp * 8 + q];
                        s += z; s2 += z * z;
                    }
                    s  += __shfl_xor_sync(0xffffffffu, s, 1);
                    s  += __shfl_xor_sync(0xffffffffu, s, 2);
                    s2 += __shfl_xor_sync(0xffffffffu, s2, 1);
                    s2 += __shfl_xor_sync(0xffffffffu, s2, 2);
                    const float mu  = s * (1.f / 32.f);
                    const float var = s2 * (1.f / 32.f) - mu * mu;
                    const float inv = rsqrtf(var + GN_EPS);
                    #pragma unroll
                    for (int q = 0; q < 4; q++) {
                        const int nf  = grp * 4 + q;
                        const int col = bc * BN + wn + nf * 8 + tg * 2;
                        float c0 = (v[nf * 2 + 0] - mu) * inv * gm[col]     + bt[col];
                        float c1 = (v[nf * 2 + 1] - mu) * inv * gm[col + 1] + bt[col + 1];
                        float2 o = { c0, c1 };
                        *(float2*)((float*)C + (size_t)row * Nn + col) = o;
                    }
                }
            }
        }
        return;
    }

    #pragma unroll
    for (int mf = 0; mf < 4; mf++) {
        #pragma unroll
        for (int nf = 0; nf < 8; nf++) {
            const int col = bc * BN + wn + nf * 8 + tg * 2;
            #pragma unroll
            for (int h = 0; h < 2; h++) {
                const int row = br * BM + wm + mf * 16 + g + h * 8;
                float c0 = acc[mf][nf][h * 2 + 0];
                float c1 = acc[mf][nf][h * 2 + 1];
                if (EPI == 2) {
                    const float2 d = *(const float2*)(Dm + (size_t)row * Nn + col);
                    c0 *= d.x; c1 *= d.y;
                } else if (EPI == 3) {
                    const float b = bias[row];
                    c0 += b; c1 += b;
                } else {
                    if (bias) { c0 += bias[col]; c1 += bias[col + 1]; }
                    if (EPI == 1) {
                        c0 = 0.5f * c0 * (1.f + erff(c0 * 0.70710678118654752f));
                        c1 = 0.5f * c1 * (1.f + erff(c1 * 0.70710678118654752f));
                    }
                }
                OutT* Cq = C + (size_t)row * Nn + col;
                if (sizeof(OutT) == 2) {
                    __half2 o = __floats2half2_rn(c0, c1);
                    *(__half2*)Cq = o;
                } else {
                    float2 o = { c0, c1 };
                    *(float2*)Cq = o;
                }
            }
        }
    }
}

// ---------------- fused prep: 5 weight transposes (fp32->fp16) + x fp32->fp16 ----------------
__global__ void prep_k(const float* __restrict__ Wq, const float* __restrict__ Wk,
                       const float* __restrict__ Wv, const float* __restrict__ Wf,
                       const float* __restrict__ Wp, const float* __restrict__ x,
                       __half* __restrict__ Wt, __half* __restrict__ xh)
{
    const int b = blockIdx.x;
    const int t = threadIdx.x;
    if (b < 1280) {
        __shared__ float tile[32][33];
        const int w  = b >> 8;                   // weight index 0..4
        const int ti = b & 255;
        const int bx = ti & 15, by = ti >> 4;
        const float* in = (w == 0) ? Wq : (w == 1) ? Wk : (w == 2) ? Wv : (w == 3) ? Wf : Wp;
        __half* out = Wt + (size_t)w * DIM * DIM;
        const int tx = t & 31, tyb = t >> 5;     // 32 x 8
        int x0 = bx * 32 + tx;
        #pragma unroll
        for (int i = 0; i < 32; i += 8)
            tile[tyb + i][tx] = in[(size_t)(by * 32 + tyb + i) * DIM + x0];
        __syncthreads();
        int x1 = by * 32 + tx;
        #pragma unroll
        for (int i = 0; i < 32; i += 8)
            out[(size_t)(bx * 32 + tyb + i) * DIM + x1] = __float2half_rn(tile[tx][tyb + i]);
    } else {
        const int i = (b - 1280) * 256 + t;      // < 1048576
        float4 v = ((const float4*)x)[i];
        __half2 a = __floats2half2_rn(v.x, v.y);
        __half2 c = __floats2half2_rn(v.z, v.w);
        uint2 o = { *(uint32_t*)&a, *(uint32_t*)&c };
        ((uint2*)xh)[i] = o;
    }
}

// ---------------- launch ----------------
extern "C" void kernel_launch(void* const* d_in, const int* in_sizes, int n_in,
                              void* d_out, int out_size)
{
    const float* x     = (const float*)d_in[0];
    const float* D     = (const float*)d_in[1];
    const float* Wq    = (const float*)d_in[2];
    const float* bq    = (const float*)d_in[3];
    const float* Wk    = (const float*)d_in[4];
    const float* bk    = (const float*)d_in[5];
    const float* Wv    = (const float*)d_in[6];
    const float* bv    = (const float*)d_in[7];
    const float* Wf    = (const float*)d_in[8];
    const float* bf    = (const float*)d_in[9];
    const float* Wp    = (const float*)d_in[10];
    const float* bp    = (const float*)d_in[11];
    const float* gamma = (const float*)d_in[12];
    const float* beta  = (const float*)d_in[13];
    float* out = (float*)d_out;

    __half *Q, *K, *Vt, *S, *X, *H, *xh, *Wt;
    cudaGetSymbolAddress((void**)&Q,  g_Q);
    cudaGetSymbolAddress((void**)&K,  g_K);
    cudaGetSymbolAddress((void**)&Vt, g_Vt);
    cudaGetSymbolAddress((void**)&S,  g_S);
    cudaGetSymbolAddress((void**)&X,  g_X);
    cudaGetSymbolAddress((void**)&H,  g_H);
    cudaGetSymbolAddress((void**)&xh, g_xh);
    cudaGetSymbolAddress((void**)&Wt, g_Wt);

    __half* Wqt = Wt + 0 * (size_t)DIM * DIM;
    __half* Wkt = Wt + 1 * (size_t)DIM * DIM;
    __half* Wvt = Wt + 2 * (size_t)DIM * DIM;
    __half* Wft = Wt + 3 * (size_t)DIM * DIM;
    __half* Wpt = Wt + 4 * (size_t)DIM * DIM;

    const int SMEM = 3 * (128 + 128) * 64 * 2;   // 98304 B per CTA
    cudaFuncSetAttribute(gemm_h<0, true,  __half>, cudaFuncAttributeMaxDynamicSharedMemorySize, SMEM);
    cudaFuncSetAttribute(gemm_h<0, false, __half>, cudaFuncAttributeMaxDynamicSharedMemorySize, SMEM);
    cudaFuncSetAttribute(gemm_h<1, false, __half>, cudaFuncAttributeMaxDynamicSharedMemorySize, SMEM);
    cudaFuncSetAttribute(gemm_h<2, false, __half>, cudaFuncAttributeMaxDynamicSharedMemorySize, SMEM);
    cudaFuncSetAttribute(gemm_h<3, false, __half>, cudaFuncAttributeMaxDynamicSharedMemorySize, SMEM);
    cudaFuncSetAttribute(gemm_h<4, false, float>,  cudaFuncAttributeMaxDynamicSharedMemorySize, SMEM);

    dim3 blk(128);
    dim3 g_thin(DIM / 128, N_TOK / 128);         // 4 x 64 = 256
    dim3 g_qk  (DIM / 128, N_TOK / 128, 2);      // 512 (Q and K batched)
    dim3 g_fat (N_TOK / 128, N_TOK / 128);       // 64 x 64 = 4096
    dim3 g_vt  (N_TOK / 128, DIM / 128);         // 64 x 4  = 256

    // 1. prep: weight transposes + x conversion
    prep_k<<<5376, 256>>>(Wq, Wk, Wv, Wf, Wp, x, Wt, xh);
    // 2. Vt[d][n] = Wv^T row d . x row n + bv[d]  (row-bias)
    gemm_h<3, false, __half><<<g_vt, blk, SMEM>>>(Wvt, xh, bv, nullptr, nullptr, nullptr,
                                                  Vt, DIM, N_TOK, DIM, nullptr, nullptr, nullptr);
    // 3. Q and K projections batched over grid.z
    gemm_h<0, true, __half><<<g_qk, blk, SMEM>>>(xh, Wqt, bq, nullptr, nullptr, nullptr,
                                                 Q, N_TOK, DIM, DIM, Wkt, bk, K);
    // 4. S = fp16( D .* (Q @ K^T) )   (plain epilogue — no hints)
    gemm_h<2, false, __half><<<g_fat, blk, SMEM>>>(Q, K, nullptr, D, nullptr, nullptr,
                                                   S, N_TOK, N_TOK, DIM, nullptr, nullptr, nullptr);
    // 5. X = fp16( S @ V ) = S @ Vt^T
    gemm_h<0, false, __half><<<g_thin, blk, SMEM>>>(S, Vt, nullptr, nullptr, nullptr, nullptr,
                                                    X, N_TOK, DIM, N_TOK, nullptr, nullptr, nullptr);
    // 6. H = fp16( gelu(X @ Wf + bf) )
    gemm_h<1, false, __half><<<g_thin, blk, SMEM>>>(X, Wft, bf, nullptr, nullptr, nullptr,
                                                    H, N_TOK, DIM, DIM, nullptr, nullptr, nullptr);
    // 7. out = GroupNorm(H @ Wp + bp) fused
    gemm_h<4, false, float><<<g_thin, blk, SMEM>>>(H, Wpt, bp, nullptr, gamma, beta,
                                                   out, N_TOK, DIM, DIM, nullptr, nullptr, nullptr);
}

// round 12
// speedup vs baseline: 1.1582x; 1.0036x over previous
#include <cuda_runtime.h>
#include <cuda_fp16.h>
#include <math.h>
#include <stdint.h>

#define N_TOK 8192
#define DIM   512
#define GN_EPS 1e-5f

// ---------------- scratch (static device arrays; runtime alloc is forbidden) ----------------
__device__ __half g_Q [(size_t)N_TOK * DIM];
__device__ __half g_K [(size_t)N_TOK * DIM];
__device__ __half g_Vt[(size_t)N_TOK * DIM];         // V transposed [DIM][N_TOK]
__device__ __half g_S [(size_t)N_TOK * N_TOK];       // 128 MB retention matrix (fp16)
__device__ __half g_X [(size_t)N_TOK * DIM];
__device__ __half g_H [(size_t)N_TOK * DIM];
__device__ __half g_xh[(size_t)N_TOK * DIM];         // fp16 x
__device__ __half g_Wt[5 * (size_t)DIM * DIM];       // transposed fp16 weights

// ---------------- helpers ----------------
__device__ __forceinline__ uint32_t smem_u32(const void* p) {
    return (uint32_t)__cvta_generic_to_shared(p);
}
__device__ __forceinline__ void cpasync16(uint32_t dst, const void* src) {
    asm volatile("cp.async.cg.shared.global [%0], [%1], 16;" :: "r"(dst), "l"(src));
}
__device__ __forceinline__ void ldmatrix_x4(uint32_t& r0, uint32_t& r1, uint32_t& r2, uint32_t& r3,
                                            uint32_t addr) {
    asm volatile("ldmatrix.sync.aligned.m8n8.x4.shared.b16 {%0,%1,%2,%3}, [%4];"
                 : "=r"(r0), "=r"(r1), "=r"(r2), "=r"(r3) : "r"(addr));
}
__device__ __forceinline__ void mma_f16(float* c, const uint32_t* a, const uint32_t* b) {
    asm volatile("mma.sync.aligned.m16n8k16.row.col.f32.f16.f16.f32 "
                 "{%0,%1,%2,%3}, {%4,%5,%6,%7}, {%8,%9}, {%0,%1,%2,%3};"
                 : "+f"(c[0]), "+f"(c[1]), "+f"(c[2]), "+f"(c[3])
                 : "r"(a[0]), "r"(a[1]), "r"(a[2]), "r"(a[3]), "r"(b[0]), "r"(b[1]));
}

// ============================================================================
// gemm_w: long-K config. 128 threads, 4 warps (2Mx2N), warp tile 64x64,
// block 128x128, BK=64, 3-stage cp.async, 2 CTAs/SM.
// EPI: 0 = +bias[col] (may be null), 2 = c * Dm[row,col]
// ============================================================================
template<int EPI, typename OutT>
__global__ __launch_bounds__(128, 2)
void gemm_w(const __half* __restrict__ A, const __half* __restrict__ B,
            const float* __restrict__ bias, const float* __restrict__ Dm,
            OutT* __restrict__ C, int M, int Nn, int Kk)
{
    constexpr int BM = 128, BN = 128, BK = 64, STAGES = 3;
    constexpr int A_BYTES = BM * BK * 2;
    constexpr int B_BYTES = BN * BK * 2;
    constexpr int STG_BYTES = A_BYTES + B_BYTES;  // 32768
    extern __shared__ char smem[];
    const uint32_t sbase = smem_u32(smem);

    const int t    = threadIdx.x;
    const int lane = t & 31;
    const int wid  = t >> 5;                      // 0..3
    const int wm   = (wid & 1) * 64;
    const int wn   = (wid >> 1) * 64;
    const int br   = blockIdx.y;
    const int bc   = blockIdx.x;

    const int lr = t >> 3;                        // 0..15 (+16 per pass)
    const int lu = t & 7;

    float acc[4][8][4];
    #pragma unroll
    for (int i = 0; i < 4; i++)
        #pragma unroll
        for (int j = 0; j < 8; j++)
            #pragma unroll
            for (int q = 0; q < 4; q++) acc[i][j][q] = 0.f;

    auto load_stage = [&](int it) {
        const uint32_t ab = sbase + (it % STAGES) * STG_BYTES;
        const uint32_t bb = ab + A_BYTES;
        const __half* Ag = A + (size_t)(br * BM) * Kk + it * BK;
        const __half* Bg = B + (size_t)(bc * BN) * Kk + it * BK;
        #pragma unroll
        for (int p = 0; p < 8; p++) {
            const int r = lr + p * 16;
            cpasync16(ab + r * 128 + ((lu ^ (r & 7)) << 4), Ag + (size_t)r * Kk + lu * 8);
        }
        #pragma unroll
        for (int p = 0; p < 8; p++) {
            const int r = lr + p * 16;
            cpasync16(bb + r * 128 + ((lu ^ (r & 7)) << 4), Bg + (size_t)r * Kk + lu * 8);
        }
        asm volatile("cp.async.commit_group;" ::: "memory");
    };

    auto compute_stage = [&](int it) {
        const uint32_t ab = sbase + (it % STAGES) * STG_BYTES;
        const uint32_t bb = ab + A_BYTES;
        const int j  = lane >> 3;
        const int rr = lane & 7;
        #pragma unroll
        for (int ks = 0; ks < 4; ks++) {
            const int ub = ks * 2;
            uint32_t af[4][4];
            #pragma unroll
            for (int mf = 0; mf < 4; mf++) {
                const int row  = wm + mf * 16 + (j & 1) * 8 + rr;
                const int unit = ub + (j >> 1);
                ldmatrix_x4(af[mf][0], af[mf][1], af[mf][2], af[mf][3],
                            ab + row * 128 + ((unit ^ (row & 7)) << 4));
            }
            uint32_t bf[8][2];
            #pragma unroll
            for (int nb = 0; nb < 4; nb++) {
                const int row  = wn + nb * 16 + (j >> 1) * 8 + rr;
                const int unit = ub + (j & 1);
                uint32_t r0, r1, r2, r3;
                ldmatrix_x4(r0, r1, r2, r3, bb + row * 128 + ((unit ^ (row & 7)) << 4));
                bf[nb * 2 + 0][0] = r0; bf[nb * 2 + 0][1] = r1;
                bf[nb * 2 + 1][0] = r2; bf[nb * 2 + 1][1] = r3;
            }
            #pragma unroll
            for (int mf = 0; mf < 4; mf++)
                #pragma unroll
                for (int nf = 0; nf < 8; nf++)
                    mma_f16(acc[mf][nf], af[mf], bf[nf]);
        }
    };

    const int nk = Kk / BK;
    load_stage(0);
    load_stage(1);
    for (int it = 0; it < nk; it++) {
        if (it + 1 < nk) asm volatile("cp.async.wait_group 1;" ::: "memory");
        else             asm volatile("cp.async.wait_group 0;" ::: "memory");
        __syncthreads();
        if (it + 2 < nk) load_stage(it + 2);
        compute_stage(it);
    }

    const int g = lane >> 2, tg = lane & 3;
    #pragma unroll
    for (int mf = 0; mf < 4; mf++) {
        #pragma unroll
        for (int nf = 0; nf < 8; nf++) {
            const int col = bc * BN + wn + nf * 8 + tg * 2;
            #pragma unroll
            for (int h = 0; h < 2; h++) {
                const int row = br * BM + wm + mf * 16 + g + h * 8;
                float c0 = acc[mf][nf][h * 2 + 0];
                float c1 = acc[mf][nf][h * 2 + 1];
                if (EPI == 2) {
                    const float2 d = *(const float2*)(Dm + (size_t)row * Nn + col);
                    c0 *= d.x; c1 *= d.y;
                } else {
                    if (bias) { c0 += bias[col]; c1 += bias[col + 1]; }
                }
                OutT* Cq = C + (size_t)row * Nn + col;
                __half2 o = __floats2half2_rn(c0, c1);
                *(__half2*)Cq = o;
            }
        }
    }
}

// ============================================================================
// gemm_h: short-K config. 256 threads, 8 warps (2Mx4N), warp tile 64x32,
// block 128x128, BK=64, 3-stage cp.async, 2 CTAs/SM (16 warps).
// EPI: 0 = +bias[col], 1 = gelu(c+bias[col]), 3 = +bias[row],
//      4 = bias[col] then fused GroupNorm (gamma/beta), fp32 out
// BATCH2: grid.z==1 selects {B2, bias2, C2}
// ============================================================================
template<int EPI, bool BATCH2, typename OutT>
__global__ __launch_bounds__(256, 2)
void gemm_h(const __half* __restrict__ A, const __half* __restrict__ Bp,
            const float* __restrict__ biasp,
            const float* __restrict__ gm, const float* __restrict__ bt,
            OutT* __restrict__ Cp, int M, int Nn, int Kk,
            const __half* __restrict__ B2, const float* __restrict__ bias2,
            OutT* __restrict__ C2)
{
    constexpr int BM = 128, BN = 128, BK = 64, STAGES = 3;
    constexpr int A_BYTES = BM * BK * 2;
    constexpr int B_BYTES = BN * BK * 2;
    constexpr int STG_BYTES = A_BYTES + B_BYTES;  // 32768
    extern __shared__ char smem[];
    const uint32_t sbase = smem_u32(smem);

    const __half* B    = Bp;
    const float*  bias = biasp;
    OutT*         C    = Cp;
    if (BATCH2 && blockIdx.z == 1) { B = B2; bias = bias2; C = C2; }

    const int t    = threadIdx.x;
    const int lane = t & 31;
    const int wid  = t >> 5;
    const int wm   = (wid & 1) * 64;              // 2 warps along M
    const int wn   = (wid >> 1) * 32;             // 4 warps along N
    const int br   = blockIdx.y;
    const int bc   = blockIdx.x;

    const int lr = t >> 3;                        // 0..31 (+32 per pass)
    const int lu = t & 7;

    float acc[4][4][4];
    #pragma unroll
    for (int i = 0; i < 4; i++)
        #pragma unroll
        for (int j = 0; j < 4; j++)
            #pragma unroll
            for (int q = 0; q < 4; q++) acc[i][j][q] = 0.f;

    auto load_stage = [&](int it) {
        const uint32_t ab = sbase + (it % STAGES) * STG_BYTES;
        const uint32_t bb = ab + A_BYTES;
        const __half* Ag = A + (size_t)(br * BM) * Kk + it * BK;
        const __half* Bg = B + (size_t)(bc * BN) * Kk + it * BK;
        #pragma unroll
        for (int p = 0; p < 4; p++) {
            const int r = lr + p * 32;
            cpasync16(ab + r * 128 + ((lu ^ (r & 7)) << 4), Ag + (size_t)r * Kk + lu * 8);
        }
        #pragma unroll
        for (int p = 0; p < 4; p++) {
            const int r = lr + p * 32;
            cpasync16(bb + r * 128 + ((lu ^ (r & 7)) << 4), Bg + (size_t)r * Kk + lu * 8);
        }
        asm volatile("cp.async.commit_group;" ::: "memory");
    };

    auto compute_stage = [&](int it) {
        const uint32_t ab = sbase + (it % STAGES) * STG_BYTES;
        const uint32_t bb = ab + A_BYTES;
        const int j  = lane >> 3;
        const int rr = lane & 7;
        #pragma unroll
        for (int ks = 0; ks < 4; ks++) {
            const int ub = ks * 2;
            uint32_t af[4][4];
            #pragma unroll
            for (int mf = 0; mf < 4; mf++) {
                const int row  = wm + mf * 16 + (j & 1) * 8 + rr;
                const int unit = ub + (j >> 1);
                ldmatrix_x4(af[mf][0], af[mf][1], af[mf][2], af[mf][3],
                            ab + row * 128 + ((unit ^ (row & 7)) << 4));
            }
            uint32_t bf[4][2];
            #pragma unroll
            for (int nb = 0; nb < 2; nb++) {
                const int row  = wn + nb * 16 + (j >> 1) * 8 + rr;
                const int unit = ub + (j & 1);
                uint32_t r0, r1, r2, r3;
                ldmatrix_x4(r0, r1, r2, r3, bb + row * 128 + ((unit ^ (row & 7)) << 4));
                bf[nb * 2 + 0][0] = r0; bf[nb * 2 + 0][1] = r1;
                bf[nb * 2 + 1][0] = r2; bf[nb * 2 + 1][1] = r3;
            }
            #pragma unroll
            for (int mf = 0; mf < 4; mf++)
                #pragma unroll
                for (int nf = 0; nf < 4; nf++)
                    mma_f16(acc[mf][nf], af[mf], bf[nf]);
        }
    };

    const int nk = Kk / BK;
    load_stage(0);
    load_stage(1);
    for (int it = 0; it < nk; it++) {
        if (it + 1 < nk) asm volatile("cp.async.wait_group 1;" ::: "memory");
        else             asm volatile("cp.async.wait_group 0;" ::: "memory");
        __syncthreads();
        if (it + 2 < nk) load_stage(it + 2);
        compute_stage(it);
    }

    const int g = lane >> 2, tg = lane & 3;

    if (EPI == 4) {
        // bias[col] + fused GroupNorm. Warp covers 32 cols == exactly one group.
        #pragma unroll
        for (int mf = 0; mf < 4; mf++) {
            #pragma unroll
            for (int h = 0; h < 2; h++) {
                const int row = br * BM + wm + mf * 16 + g + h * 8;
                float v[8];
                #pragma unroll
                for (int nf = 0; nf < 4; nf++) {
                    const int col = bc * BN + wn + nf * 8 + tg * 2;
                    v[nf * 2 + 0] = acc[mf][nf][h * 2 + 0] + bias[col];
                    v[nf * 2 + 1] = acc[mf][nf][h * 2 + 1] + bias[col + 1];
                }
                float s = 0.f, s2 = 0.f;
                #pragma unroll
                for (int q = 0; q < 8; q++) { s += v[q]; s2 += v[q] * v[q]; }
                s  += __shfl_xor_sync(0xffffffffu, s, 1);
                s  += __shfl_xor_sync(0xffffffffu, s, 2);
                s2 += __shfl_xor_sync(0xffffffffu, s2, 1);
                s2 += __shfl_xor_sync(0xffffffffu, s2, 2);
                const float mu  = s * (1.f / 32.f);
                const float var = s2 * (1.f / 32.f) - mu * mu;
                const float inv = rsqrtf(var + GN_EPS);
                #pragma unroll
                for (int nf = 0; nf < 4; nf++) {
                    const int col = bc * BN + wn + nf * 8 + tg * 2;
                    float c0 = (v[nf * 2 + 0] - mu) * inv * gm[col]     + bt[col];
                    float c1 = (v[nf * 2 + 1] - mu) * inv * gm[col + 1] + bt[col + 1];
                    float2 o = { c0, c1 };
                    *(float2*)((float*)C + (size_t)row * Nn + col) = o;
                }
            }
        }
        return;
    }

    #pragma unroll
    for (int mf = 0; mf < 4; mf++) {
        #pragma unroll
        for (int nf = 0; nf < 4; nf++) {
            const int col = bc * BN + wn + nf * 8 + tg * 2;
            #pragma unroll
            for (int h = 0; h < 2; h++) {
                const int row = br * BM + wm + mf * 16 + g + h * 8;
                float c0 = acc[mf][nf][h * 2 + 0];
                float c1 = acc[mf][nf][h * 2 + 1];
                if (EPI == 3) {
                    const float b = bias[row];
                    c0 += b; c1 += b;
                } else {
                    if (bias) { c0 += bias[col]; c1 += bias[col + 1]; }
                    if (EPI == 1) {
                        c0 = 0.5f * c0 * (1.f + erff(c0 * 0.70710678118654752f));
                        c1 = 0.5f * c1 * (1.f + erff(c1 * 0.70710678118654752f));
                    }
                }
                OutT* Cq = C + (size_t)row * Nn + col;
                __half2 o = __floats2half2_rn(c0, c1);
                *(__half2*)Cq = o;
            }
        }
    }
}

// ---------------- fused prep: 5 weight transposes (fp32->fp16) + x fp32->fp16 ----------------
__global__ void prep_k(const float* __restrict__ Wq, const float* __restrict__ Wk,
                       const float* __restrict__ Wv, const float* __restrict__ Wf,
                       const float* __restrict__ Wp, const float* __restrict__ x,
                       __half* __restrict__ Wt, __half* __restrict__ xh)
{
    const int b = blockIdx.x;
    const int t = threadIdx.x;
    if (b < 1280) {
        __shared__ float tile[32][33];
        const int w  = b >> 8;                   // weight index 0..4
        const int ti = b & 255;
        const int bx = ti & 15, by = ti >> 4;
        const float* in = (w == 0) ? Wq : (w == 1) ? Wk : (w == 2) ? Wv : (w == 3) ? Wf : Wp;
        __half* out = Wt + (size_t)w * DIM * DIM;
        const int tx = t & 31, tyb = t >> 5;     // 32 x 8
        int x0 = bx * 32 + tx;
        #pragma unroll
        for (int i = 0; i < 32; i += 8)
            tile[tyb + i][tx] = in[(size_t)(by * 32 + tyb + i) * DIM + x0];
        __syncthreads();
        int x1 = by * 32 + tx;
        #pragma unroll
        for (int i = 0; i < 32; i += 8)
            out[(size_t)(bx * 32 + tyb + i) * DIM + x1] = __float2half_rn(tile[tx][tyb + i]);
    } else {
        const int i = (b - 1280) * 256 + t;      // < 1048576
        float4 v = ((const float4*)x)[i];
        __half2 a = __floats2half2_rn(v.x, v.y);
        __half2 c = __floats2half2_rn(v.z, v.w);
        uint2 o = { *(uint32_t*)&a, *(uint32_t*)&c };
        ((uint2*)xh)[i] = o;
    }
}

// ---------------- launch ----------------
extern "C" void kernel_launch(void* const* d_in, const int* in_sizes, int n_in,
                              void* d_out, int out_size)
{
    const float* x     = (const float*)d_in[0];
    const float* D     = (const float*)d_in[1];
    const float* Wq    = (const float*)d_in[2];
    const float* bq    = (const float*)d_in[3];
    const float* Wk    = (const float*)d_in[4];
    const float* bk    = (const float*)d_in[5];
    const float* Wv    = (const float*)d_in[6];
    const float* bv    = (const float*)d_in[7];
    const float* Wf    = (const float*)d_in[8];
    const float* bf    = (const float*)d_in[9];
    const float* Wp    = (const float*)d_in[10];
    const float* bp    = (const float*)d_in[11];
    const float* gamma = (const float*)d_in[12];
    const float* beta  = (const float*)d_in[13];
    float* out = (float*)d_out;

    __half *Q, *K, *Vt, *S, *X, *H, *xh, *Wt;
    cudaGetSymbolAddress((void**)&Q,  g_Q);
    cudaGetSymbolAddress((void**)&K,  g_K);
    cudaGetSymbolAddress((void**)&Vt, g_Vt);
    cudaGetSymbolAddress((void**)&S,  g_S);
    cudaGetSymbolAddress((void**)&X,  g_X);
    cudaGetSymbolAddress((void**)&H,  g_H);
    cudaGetSymbolAddress((void**)&xh, g_xh);
    cudaGetSymbolAddress((void**)&Wt, g_Wt);

    __half* Wqt = Wt + 0 * (size_t)DIM * DIM;
    __half* Wkt = Wt + 1 * (size_t)DIM * DIM;
    __half* Wvt = Wt + 2 * (size_t)DIM * DIM;
    __half* Wft = Wt + 3 * (size_t)DIM * DIM;
    __half* Wpt = Wt + 4 * (size_t)DIM * DIM;

    const int SMEM = 3 * (128 + 128) * 64 * 2;   // 98304 B per CTA
    cudaFuncSetAttribute(gemm_w<0, __half>, cudaFuncAttributeMaxDynamicSharedMemorySize, SMEM);
    cudaFuncSetAttribute(gemm_w<2, __half>, cudaFuncAttributeMaxDynamicSharedMemorySize, SMEM);
    cudaFuncSetAttribute(gemm_h<0, true,  __half>, cudaFuncAttributeMaxDynamicSharedMemorySize, SMEM);
    cudaFuncSetAttribute(gemm_h<1, false, __half>, cudaFuncAttributeMaxDynamicSharedMemorySize, SMEM);
    cudaFuncSetAttribute(gemm_h<3, false, __half>, cudaFuncAttributeMaxDynamicSharedMemorySize, SMEM);
    cudaFuncSetAttribute(gemm_h<4, false, float>,  cudaFuncAttributeMaxDynamicSharedMemorySize, SMEM);

    dim3 blkH(256), blkW(128);
    dim3 g_thin(DIM / 128, N_TOK / 128);         // 4 x 64 = 256
    dim3 g_qk  (DIM / 128, N_TOK / 128, 2);      // 512 (Q and K batched)
    dim3 g_fat (N_TOK / 128, N_TOK / 128);       // 64 x 64 = 4096
    dim3 g_vt  (N_TOK / 128, DIM / 128);         // 64 x 4  = 256

    // 1. prep: weight transposes + x conversion
    prep_k<<<5376, 256>>>(Wq, Wk, Wv, Wf, Wp, x, Wt, xh);
    // 2. Vt[d][n] = Wv^T row d . x row n + bv[d]  (row-bias; short-K config)
    gemm_h<3, false, __half><<<g_vt, blkH, SMEM>>>(Wvt, xh, bv, nullptr, nullptr,
                                                   Vt, DIM, N_TOK, DIM, nullptr, nullptr, nullptr);
    // 3. Q and K projections batched over grid.z (short-K config)
    gemm_h<0, true, __half><<<g_qk, blkH, SMEM>>>(xh, Wqt, bq, nullptr, nullptr,
                                                  Q, N_TOK, DIM, DIM, Wkt, bk, K);
    // 4. S = fp16( D .* (Q @ K^T) )  (long-run config, 64x64 warp tile)
    gemm_w<2, __half><<<g_fat, blkW, SMEM>>>(Q, K, nullptr, D, S, N_TOK, N_TOK, DIM);
    // 5. X = fp16( S @ V ) = S @ Vt^T  (K=8192: long-K config)
    gemm_w<0, __half><<<g_thin, blkW, SMEM>>>(S, Vt, nullptr, nullptr, X, N_TOK, DIM, N_TOK);
    // 6. H = fp16( gelu(X @ Wf + bf) )  (short-K config)
    gemm_h<1, false, __half><<<g_thin, blkH, SMEM>>>(X, Wft, bf, nullptr, nullptr,
                                                     H, N_TOK, DIM, DIM, nullptr, nullptr, nullptr);
    // 7. out = GroupNorm(H @ Wp + bp) fused (short-K config)
    gemm_h<4, false, float><<<g_thin, blkH, SMEM>>>(H, Wpt, bp, gamma, beta,
                                                    out, N_TOK, DIM, DIM, nullptr, nullptr, nullptr);
}

// round 13
// speedup vs baseline: 1.1589x; 1.0007x over previous
#include <cuda_runtime.h>
#include <cuda_fp16.h>
#include <math.h>
#include <stdint.h>

#define N_TOK 8192
#define DIM   512
#define GN_EPS 1e-5f

// ---------------- scratch (static device arrays; runtime alloc is forbidden) ----------------
__device__ __half g_Q [(size_t)N_TOK * DIM];
__device__ __half g_K [(size_t)N_TOK * DIM];
__device__ __half g_Vt[(size_t)N_TOK * DIM];         // V transposed [DIM][N_TOK]
__device__ __half g_S [(size_t)N_TOK * N_TOK];       // 128 MB retention matrix (fp16)
__device__ __half g_X [(size_t)N_TOK * DIM];
__device__ __half g_H [(size_t)N_TOK * DIM];
__device__ __half g_xh[(size_t)N_TOK * DIM];         // fp16 x
__device__ __half g_Wt[5 * (size_t)DIM * DIM];       // transposed fp16 weights

// ---------------- helpers ----------------
__device__ __forceinline__ uint32_t smem_u32(const void* p) {
    return (uint32_t)__cvta_generic_to_shared(p);
}
__device__ __forceinline__ void cpasync16(uint32_t dst, const void* src) {
    asm volatile("cp.async.cg.shared.global [%0], [%1], 16;" :: "r"(dst), "l"(src));
}
__device__ __forceinline__ void ldmatrix_x4(uint32_t& r0, uint32_t& r1, uint32_t& r2, uint32_t& r3,
                                            uint32_t addr) {
    asm volatile("ldmatrix.sync.aligned.m8n8.x4.shared.b16 {%0,%1,%2,%3}, [%4];"
                 : "=r"(r0), "=r"(r1), "=r"(r2), "=r"(r3) : "r"(addr));
}
__device__ __forceinline__ void mma_f16(float* c, const uint32_t* a, const uint32_t* b) {
    asm volatile("mma.sync.aligned.m16n8k16.row.col.f32.f16.f16.f32 "
                 "{%0,%1,%2,%3}, {%4,%5,%6,%7}, {%8,%9}, {%0,%1,%2,%3};"
                 : "+f"(c[0]), "+f"(c[1]), "+f"(c[2]), "+f"(c[3])
                 : "r"(a[0]), "r"(a[1]), "r"(a[2]), "r"(a[3]), "r"(b[0]), "r"(b[1]));
}

// ============================================================================
// gemm_w: L2-resident long-K config (QK^T only). 128 threads, 4 warps (2Mx2N),
// warp tile 64x64, block 128x128, BK=64, 3-stage cp.async, 2 CTAs/SM.
// EPI: 2 = c * Dm[row,col]
// ============================================================================
template<int EPI, typename OutT>
__global__ __launch_bounds__(128, 2)
void gemm_w(const __half* __restrict__ A, const __half* __restrict__ B,
            const float* __restrict__ bias, const float* __restrict__ Dm,
            OutT* __restrict__ C, int M, int Nn, int Kk)
{
    constexpr int BM = 128, BN = 128, BK = 64, STAGES = 3;
    constexpr int A_BYTES = BM * BK * 2;
    constexpr int B_BYTES = BN * BK * 2;
    constexpr int STG_BYTES = A_BYTES + B_BYTES;  // 32768
    extern __shared__ char smem[];
    const uint32_t sbase = smem_u32(smem);

    const int t    = threadIdx.x;
    const int lane = t & 31;
    const int wid  = t >> 5;                      // 0..3
    const int wm   = (wid & 1) * 64;
    const int wn   = (wid >> 1) * 64;
    const int br   = blockIdx.y;
    const int bc   = blockIdx.x;

    const int lr = t >> 3;                        // 0..15 (+16 per pass)
    const int lu = t & 7;

    float acc[4][8][4];
    #pragma unroll
    for (int i = 0; i < 4; i++)
        #pragma unroll
        for (int j = 0; j < 8; j++)
            #pragma unroll
            for (int q = 0; q < 4; q++) acc[i][j][q] = 0.f;

    auto load_stage = [&](int it) {
        const uint32_t ab = sbase + (it % STAGES) * STG_BYTES;
        const uint32_t bb = ab + A_BYTES;
        const __half* Ag = A + (size_t)(br * BM) * Kk + it * BK;
        const __half* Bg = B + (size_t)(bc * BN) * Kk + it * BK;
        #pragma unroll
        for (int p = 0; p < 8; p++) {
            const int r = lr + p * 16;
            cpasync16(ab + r * 128 + ((lu ^ (r & 7)) << 4), Ag + (size_t)r * Kk + lu * 8);
        }
        #pragma unroll
        for (int p = 0; p < 8; p++) {
            const int r = lr + p * 16;
            cpasync16(bb + r * 128 + ((lu ^ (r & 7)) << 4), Bg + (size_t)r * Kk + lu * 8);
        }
        asm volatile("cp.async.commit_group;" ::: "memory");
    };

    auto compute_stage = [&](int it) {
        const uint32_t ab = sbase + (it % STAGES) * STG_BYTES;
        const uint32_t bb = ab + A_BYTES;
        const int j  = lane >> 3;
        const int rr = lane & 7;
        #pragma unroll
        for (int ks = 0; ks < 4; ks++) {
            const int ub = ks * 2;
            uint32_t af[4][4];
            #pragma unroll
            for (int mf = 0; mf < 4; mf++) {
                const int row  = wm + mf * 16 + (j & 1) * 8 + rr;
                const int unit = ub + (j >> 1);
                ldmatrix_x4(af[mf][0], af[mf][1], af[mf][2], af[mf][3],
                            ab + row * 128 + ((unit ^ (row & 7)) << 4));
            }
            uint32_t bf[8][2];
            #pragma unroll
            for (int nb = 0; nb < 4; nb++) {
                const int row  = wn + nb * 16 + (j >> 1) * 8 + rr;
                const int unit = ub + (j & 1);
                uint32_t r0, r1, r2, r3;
                ldmatrix_x4(r0, r1, r2, r3, bb + row * 128 + ((unit ^ (row & 7)) << 4));
                bf[nb * 2 + 0][0] = r0; bf[nb * 2 + 0][1] = r1;
                bf[nb * 2 + 1][0] = r2; bf[nb * 2 + 1][1] = r3;
            }
            #pragma unroll
            for (int mf = 0; mf < 4; mf++)
                #pragma unroll
                for (int nf = 0; nf < 8; nf++)
                    mma_f16(acc[mf][nf], af[mf], bf[nf]);
        }
    };

    const int nk = Kk / BK;
    load_stage(0);
    load_stage(1);
    for (int it = 0; it < nk; it++) {
        if (it + 1 < nk) asm volatile("cp.async.wait_group 1;" ::: "memory");
        else             asm volatile("cp.async.wait_group 0;" ::: "memory");
        __syncthreads();
        if (it + 2 < nk) load_stage(it + 2);
        compute_stage(it);
    }

    const int g = lane >> 2, tg = lane & 3;
    #pragma unroll
    for (int mf = 0; mf < 4; mf++) {
        #pragma unroll
        for (int nf = 0; nf < 8; nf++) {
            const int col = bc * BN + wn + nf * 8 + tg * 2;
            #pragma unroll
            for (int h = 0; h < 2; h++) {
                const int row = br * BM + wm + mf * 16 + g + h * 8;
                float c0 = acc[mf][nf][h * 2 + 0];
                float c1 = acc[mf][nf][h * 2 + 1];
                if (EPI == 2) {
                    const float2 d = *(const float2*)(Dm + (size_t)row * Nn + col);
                    c0 *= d.x; c1 *= d.y;
                } else {
                    if (bias) { c0 += bias[col]; c1 += bias[col + 1]; }
                }
                OutT* Cq = C + (size_t)row * Nn + col;
                __half2 o = __floats2half2_rn(c0, c1);
                *(__half2*)Cq = o;
            }
        }
    }
}

// ============================================================================
// gemm_h: general config. 256 threads, 8 warps (2Mx4N), warp tile 64x32,
// block 128x128, BK=64, 3-stage cp.async, 2 CTAs/SM (16 warps).
// EPI: 0 = +bias[col], 1 = gelu(c+bias[col]), 3 = +bias[row],
//      4 = bias[col] then fused GroupNorm (gamma/beta), fp32 out
// BATCH2: grid.z==1 selects {B2, bias2, C2}
// ============================================================================
template<int EPI, bool BATCH2, typename OutT>
__global__ __launch_bounds__(256, 2)
void gemm_h(const __half* __restrict__ A, const __half* __restrict__ Bp,
            const float* __restrict__ biasp,
            const float* __restrict__ gm, const float* __restrict__ bt,
            OutT* __restrict__ Cp, int M, int Nn, int Kk,
            const __half* __restrict__ B2, const float* __restrict__ bias2,
            OutT* __restrict__ C2)
{
    constexpr int BM = 128, BN = 128, BK = 64, STAGES = 3;
    constexpr int A_BYTES = BM * BK * 2;
    constexpr int B_BYTES = BN * BK * 2;
    constexpr int STG_BYTES = A_BYTES + B_BYTES;  // 32768
    extern __shared__ char smem[];
    const uint32_t sbase = smem_u32(smem);

    const __half* B    = Bp;
    const float*  bias = biasp;
    OutT*         C    = Cp;
    if (BATCH2 && blockIdx.z == 1) { B = B2; bias = bias2; C = C2; }

    const int t    = threadIdx.x;
    const int lane = t & 31;
    const int wid  = t >> 5;
    const int wm   = (wid & 1) * 64;              // 2 warps along M
    const int wn   = (wid >> 1) * 32;             // 4 warps along N
    const int br   = blockIdx.y;
    const int bc   = blockIdx.x;

    const int lr = t >> 3;                        // 0..31 (+32 per pass)
    const int lu = t & 7;

    float acc[4][4][4];
    #pragma unroll
    for (int i = 0; i < 4; i++)
        #pragma unroll
        for (int j = 0; j < 4; j++)
            #pragma unroll
            for (int q = 0; q < 4; q++) acc[i][j][q] = 0.f;

    auto load_stage = [&](int it) {
        const uint32_t ab = sbase + (it % STAGES) * STG_BYTES;
        const uint32_t bb = ab + A_BYTES;
        const __half* Ag = A + (size_t)(br * BM) * Kk + it * BK;
        const __half* Bg = B + (size_t)(bc * BN) * Kk + it * BK;
        #pragma unroll
        for (int p = 0; p < 4; p++) {
            const int r = lr + p * 32;
            cpasync16(ab + r * 128 + ((lu ^ (r & 7)) << 4), Ag + (size_t)r * Kk + lu * 8);
        }
        #pragma unroll
        for (int p = 0; p < 4; p++) {
            const int r = lr + p * 32;
            cpasync16(bb + r * 128 + ((lu ^ (r & 7)) << 4), Bg + (size_t)r * Kk + lu * 8);
        }
        asm volatile("cp.async.commit_group;" ::: "memory");
    };

    auto compute_stage = [&](int it) {
        const uint32_t ab = sbase + (it % STAGES) * STG_BYTES;
        const uint32_t bb = ab + A_BYTES;
        const int j  = lane >> 3;
        const int rr = lane & 7;
        #pragma unroll
        for (int ks = 0; ks < 4; ks++) {
            const int ub = ks * 2;
            uint32_t af[4][4];
            #pragma unroll
            for (int mf = 0; mf < 4; mf++) {
                const int row  = wm + mf * 16 + (j & 1) * 8 + rr;
                const int unit = ub + (j >> 1);
                ldmatrix_x4(af[mf][0], af[mf][1], af[mf][2], af[mf][3],
                            ab + row * 128 + ((unit ^ (row & 7)) << 4));
            }
            uint32_t bf[4][2];
            #pragma unroll
            for (int nb = 0; nb < 2; nb++) {
                const int row  = wn + nb * 16 + (j >> 1) * 8 + rr;
                const int unit = ub + (j & 1);
                uint32_t r0, r1, r2, r3;
                ldmatrix_x4(r0, r1, r2, r3, bb + row * 128 + ((unit ^ (row & 7)) << 4));
                bf[nb * 2 + 0][0] = r0; bf[nb * 2 + 0][1] = r1;
                bf[nb * 2 + 1][0] = r2; bf[nb * 2 + 1][1] = r3;
            }
            #pragma unroll
            for (int mf = 0; mf < 4; mf++)
                #pragma unroll
                for (int nf = 0; nf < 4; nf++)
                    mma_f16(acc[mf][nf], af[mf], bf[nf]);
        }
    };

    const int nk = Kk / BK;
    load_stage(0);
    load_stage(1);
    for (int it = 0; it < nk; it++) {
        if (it + 1 < nk) asm volatile("cp.async.wait_group 1;" ::: "memory");
        else             asm volatile("cp.async.wait_group 0;" ::: "memory");
        __syncthreads();
        if (it + 2 < nk) load_stage(it + 2);
        compute_stage(it);
    }

    const int g = lane >> 2, tg = lane & 3;

    if (EPI == 4) {
        // bias[col] + fused GroupNorm. Warp covers 32 cols == exactly one group.
        #pragma unroll
        for (int mf = 0; mf < 4; mf++) {
            #pragma unroll
            for (int h = 0; h < 2; h++) {
                const int row = br * BM + wm + mf * 16 + g + h * 8;
                float v[8];
                #pragma unroll
                for (int nf = 0; nf < 4; nf++) {
                    const int col = bc * BN + wn + nf * 8 + tg * 2;
                    v[nf * 2 + 0] = acc[mf][nf][h * 2 + 0] + bias[col];
                    v[nf * 2 + 1] = acc[mf][nf][h * 2 + 1] + bias[col + 1];
                }
                float s = 0.f, s2 = 0.f;
                #pragma unroll
                for (int q = 0; q < 8; q++) { s += v[q]; s2 += v[q] * v[q]; }
                s  += __shfl_xor_sync(0xffffffffu, s, 1);
                s  += __shfl_xor_sync(0xffffffffu, s, 2);
                s2 += __shfl_xor_sync(0xffffffffu, s2, 1);
                s2 += __shfl_xor_sync(0xffffffffu, s2, 2);
                const float mu  = s * (1.f / 32.f);
                const float var = s2 * (1.f / 32.f) - mu * mu;
                const float inv = rsqrtf(var + GN_EPS);
                #pragma unroll
                for (int nf = 0; nf < 4; nf++) {
                    const int col = bc * BN + wn + nf * 8 + tg * 2;
                    float c0 = (v[nf * 2 + 0] - mu) * inv * gm[col]     + bt[col];
                    float c1 = (v[nf * 2 + 1] - mu) * inv * gm[col + 1] + bt[col + 1];
                    float2 o = { c0, c1 };
                    *(float2*)((float*)C + (size_t)row * Nn + col) = o;
                }
            }
        }
        return;
    }

    #pragma unroll
    for (int mf = 0; mf < 4; mf++) {
        #pragma unroll
        for (int nf = 0; nf < 4; nf++) {
            const int col = bc * BN + wn + nf * 8 + tg * 2;
            #pragma unroll
            for (int h = 0; h < 2; h++) {
                const int row = br * BM + wm + mf * 16 + g + h * 8;
                float c0 = acc[mf][nf][h * 2 + 0];
                float c1 = acc[mf][nf][h * 2 + 1];
                if (EPI == 3) {
                    const float b = bias[row];
                    c0 += b; c1 += b;
                } else {
                    if (bias) { c0 += bias[col]; c1 += bias[col + 1]; }
                    if (EPI == 1) {
                        c0 = 0.5f * c0 * (1.f + erff(c0 * 0.70710678118654752f));
                        c1 = 0.5f * c1 * (1.f + erff(c1 * 0.70710678118654752f));
                    }
                }
                OutT* Cq = C + (size_t)row * Nn + col;
                __half2 o = __floats2half2_rn(c0, c1);
                *(__half2*)Cq = o;
            }
        }
    }
}

// ---------------- fused prep: 5 weight transposes (fp32->fp16) + x fp32->fp16 ----------------
__global__ void prep_k(const float* __restrict__ Wq, const float* __restrict__ Wk,
                       const float* __restrict__ Wv, const float* __restrict__ Wf,
                       const float* __restrict__ Wp, const float* __restrict__ x,
                       __half* __restrict__ Wt, __half* __restrict__ xh)
{
    const int b = blockIdx.x;
    const int t = threadIdx.x;
    if (b < 1280) {
        __shared__ float tile[32][33];
        const int w  = b >> 8;                   // weight index 0..4
        const int ti = b & 255;
        const int bx = ti & 15, by = ti >> 4;
        const float* in = (w == 0) ? Wq : (w == 1) ? Wk : (w == 2) ? Wv : (w == 3) ? Wf : Wp;
        __half* out = Wt + (size_t)w * DIM * DIM;
        const int tx = t & 31, tyb = t >> 5;     // 32 x 8
        int x0 = bx * 32 + tx;
        #pragma unroll
        for (int i = 0; i < 32; i += 8)
            tile[tyb + i][tx] = in[(size_t)(by * 32 + tyb + i) * DIM + x0];
        __syncthreads();
        int x1 = by * 32 + tx;
        #pragma unroll
        for (int i = 0; i < 32; i += 8)
            out[(size_t)(bx * 32 + tyb + i) * DIM + x1] = __float2half_rn(tile[tx][tyb + i]);
    } else {
        const int i = (b - 1280) * 256 + t;      // < 1048576
        float4 v = ((const float4*)x)[i];
        __half2 a = __floats2half2_rn(v.x, v.y);
        __half2 c = __floats2half2_rn(v.z, v.w);
        uint2 o = { *(uint32_t*)&a, *(uint32_t*)&c };
        ((uint2*)xh)[i] = o;
    }
}

// ---------------- launch ----------------
extern "C" void kernel_launch(void* const* d_in, const int* in_sizes, int n_in,
                              void* d_out, int out_size)
{
    const float* x     = (const float*)d_in[0];
    const float* D     = (const float*)d_in[1];
    const float* Wq    = (const float*)d_in[2];
    const float* bq    = (const float*)d_in[3];
    const float* Wk    = (const float*)d_in[4];
    const float* bk    = (const float*)d_in[5];
    const float* Wv    = (const float*)d_in[6];
    const float* bv    = (const float*)d_in[7];
    const float* Wf    = (const float*)d_in[8];
    const float* bf    = (const float*)d_in[9];
    const float* Wp    = (const float*)d_in[10];
    const float* bp    = (const float*)d_in[11];
    const float* gamma = (const float*)d_in[12];
    const float* beta  = (const float*)d_in[13];
    float* out = (float*)d_out;

    __half *Q, *K, *Vt, *S, *X, *H, *xh, *Wt;
    cudaGetSymbolAddress((void**)&Q,  g_Q);
    cudaGetSymbolAddress((void**)&K,  g_K);
    cudaGetSymbolAddress((void**)&Vt, g_Vt);
    cudaGetSymbolAddress((void**)&S,  g_S);
    cudaGetSymbolAddress((void**)&X,  g_X);
    cudaGetSymbolAddress((void**)&H,  g_H);
    cudaGetSymbolAddress((void**)&xh, g_xh);
    cudaGetSymbolAddress((void**)&Wt, g_Wt);

    __half* Wqt = Wt + 0 * (size_t)DIM * DIM;
    __half* Wkt = Wt + 1 * (size_t)DIM * DIM;
    __half* Wvt = Wt + 2 * (size_t)DIM * DIM;
    __half* Wft = Wt + 3 * (size_t)DIM * DIM;
    __half* Wpt = Wt + 4 * (size_t)DIM * DIM;

    const int SMEM = 3 * (128 + 128) * 64 * 2;   // 98304 B per CTA
    cudaFuncSetAttribute(gemm_w<2, __half>, cudaFuncAttributeMaxDynamicSharedMemorySize, SMEM);
    cudaFuncSetAttribute(gemm_h<0, true,  __half>, cudaFuncAttributeMaxDynamicSharedMemorySize, SMEM);
    cudaFuncSetAttribute(gemm_h<0, false, __half>, cudaFuncAttributeMaxDynamicSharedMemorySize, SMEM);
    cudaFuncSetAttribute(gemm_h<1, false, __half>, cudaFuncAttributeMaxDynamicSharedMemorySize, SMEM);
    cudaFuncSetAttribute(gemm_h<3, false, __half>, cudaFuncAttributeMaxDynamicSharedMemorySize, SMEM);
    cudaFuncSetAttribute(gemm_h<4, false, float>,  cudaFuncAttributeMaxDynamicSharedMemorySize, SMEM);

    dim3 blkH(256), blkW(128);
    dim3 g_thin(DIM / 128, N_TOK / 128);         // 4 x 64 = 256
    dim3 g_qk  (DIM / 128, N_TOK / 128, 2);      // 512 (Q and K batched)
    dim3 g_fat (N_TOK / 128, N_TOK / 128);       // 64 x 64 = 4096
    dim3 g_vt  (N_TOK / 128, DIM / 128);         // 64 x 4  = 256

    // 1. prep: weight transposes + x conversion
    prep_k<<<5376, 256>>>(Wq, Wk, Wv, Wf, Wp, x, Wt, xh);
    // 2. Vt[d][n] = Wv^T row d . x row n + bv[d]  (row-bias)
    gemm_h<3, false, __half><<<g_vt, blkH, SMEM>>>(Wvt, xh, bv, nullptr, nullptr,
                                                   Vt, DIM, N_TOK, DIM, nullptr, nullptr, nullptr);
    // 3. Q and K projections batched over grid.z
    gemm_h<0, true, __half><<<g_qk, blkH, SMEM>>>(xh, Wqt, bq, nullptr, nullptr,
                                                  Q, N_TOK, DIM, DIM, Wkt, bk, K);
    // 4. S = fp16( D .* (Q @ K^T) )  -- gemm_w: L2-resident Q/K, long feed-bound loop
    gemm_w<2, __half><<<g_fat, blkW, SMEM>>>(Q, K, nullptr, D, S, N_TOK, N_TOK, DIM);
    // 5. X = fp16( S @ V ) = S @ Vt^T  -- gemm_h: DRAM-streaming S needs 16 warps/SM
    gemm_h<0, false, __half><<<g_thin, blkH, SMEM>>>(S, Vt, nullptr, nullptr, nullptr,
                                                     X, N_TOK, DIM, N_TOK, nullptr, nullptr, nullptr);
    // 6. H = fp16( gelu(X @ Wf + bf) )
    gemm_h<1, false, __half><<<g_thin, blkH, SMEM>>>(X, Wft, bf, nullptr, nullptr,
                                                     H, N_TOK, DIM, DIM, nullptr, nullptr, nullptr);
    // 7. out = GroupNorm(H @ Wp + bp) fused
    gemm_h<4, false, float><<<g_thin, blkH, SMEM>>>(H, Wpt, bp, gamma, beta,
                                                    out, N_TOK, DIM, DIM, nullptr, nullptr, nullptr);
}

// round 14
// speedup vs baseline: 1.1633x; 1.0038x over previous
#include <cuda_runtime.h>
#include <cuda_fp16.h>
#include <math.h>
#include <stdint.h>

#define N_TOK 8192
#define DIM   512
#define GN_EPS 1e-5f

// ---------------- scratch (static device arrays; runtime alloc is forbidden) ----------------
__device__ __half g_Q [(size_t)N_TOK * DIM];
__device__ __half g_K [(size_t)N_TOK * DIM];
__device__ __half g_Vt[(size_t)N_TOK * DIM];         // V transposed [DIM][N_TOK]
__device__ __half g_S [(size_t)N_TOK * N_TOK];       // 128 MB retention matrix (fp16)
__device__ __half g_X [(size_t)N_TOK * DIM];
__device__ __half g_H [(size_t)N_TOK * DIM];
__device__ __half g_xh[(size_t)N_TOK * DIM];         // fp16 x
__device__ __half g_Wt[5 * (size_t)DIM * DIM];       // transposed fp16 weights

// ---------------- helpers ----------------
__device__ __forceinline__ uint32_t smem_u32(const void* p) {
    return (uint32_t)__cvta_generic_to_shared(p);
}
__device__ __forceinline__ void cpasync16(uint32_t dst, const void* src) {
    asm volatile("cp.async.cg.shared.global [%0], [%1], 16;" :: "r"(dst), "l"(src));
}
__device__ __forceinline__ void ldmatrix_x4(uint32_t& r0, uint32_t& r1, uint32_t& r2, uint32_t& r3,
                                            uint32_t addr) {
    asm volatile("ldmatrix.sync.aligned.m8n8.x4.shared.b16 {%0,%1,%2,%3}, [%4];"
                 : "=r"(r0), "=r"(r1), "=r"(r2), "=r"(r3) : "r"(addr));
}
__device__ __forceinline__ void mma_f16(float* c, const uint32_t* a, const uint32_t* b) {
    asm volatile("mma.sync.aligned.m16n8k16.row.col.f32.f16.f16.f32 "
                 "{%0,%1,%2,%3}, {%4,%5,%6,%7}, {%8,%9}, {%0,%1,%2,%3};"
                 : "+f"(c[0]), "+f"(c[1]), "+f"(c[2]), "+f"(c[3])
                 : "r"(a[0]), "r"(a[1]), "r"(a[2]), "r"(a[3]), "r"(b[0]), "r"(b[1]));
}

// ============================================================================
// gemm_w: QK^T config. 128 threads, 4 warps (2Mx2N), warp tile 64x64,
// block 128x128, BK=64, 3-stage cp.async, 2 CTAs/SM. EPI fixed: c * Dm.
// ============================================================================
__global__ __launch_bounds__(128, 2)
void gemm_w(const __half* __restrict__ A, const __half* __restrict__ B,
            const float* __restrict__ Dm,
            __half* __restrict__ C, int M, int Nn, int Kk)
{
    constexpr int BM = 128, BN = 128, BK = 64, STAGES = 3;
    constexpr int A_BYTES = BM * BK * 2;
    constexpr int B_BYTES = BN * BK * 2;
    constexpr int STG_BYTES = A_BYTES + B_BYTES;  // 32768
    extern __shared__ char smem[];
    const uint32_t sbase = smem_u32(smem);

    const int t    = threadIdx.x;
    const int lane = t & 31;
    const int wid  = t >> 5;                      // 0..3
    const int wm   = (wid & 1) * 64;
    const int wn   = (wid >> 1) * 64;
    const int br   = blockIdx.y;
    const int bc   = blockIdx.x;

    const int lr = t >> 3;                        // 0..15 (+16 per pass)
    const int lu = t & 7;

    float acc[4][8][4];
    #pragma unroll
    for (int i = 0; i < 4; i++)
        #pragma unroll
        for (int j = 0; j < 8; j++)
            #pragma unroll
            for (int q = 0; q < 4; q++) acc[i][j][q] = 0.f;

    auto load_stage = [&](int it) {
        const uint32_t ab = sbase + (it % STAGES) * STG_BYTES;
        const uint32_t bb = ab + A_BYTES;
        const __half* Ag = A + (size_t)(br * BM) * Kk + it * BK;
        const __half* Bg = B + (size_t)(bc * BN) * Kk + it * BK;
        #pragma unroll
        for (int p = 0; p < 8; p++) {
            const int r = lr + p * 16;
            cpasync16(ab + r * 128 + ((lu ^ (r & 7)) << 4), Ag + (size_t)r * Kk + lu * 8);
        }
        #pragma unroll
        for (int p = 0; p < 8; p++) {
            const int r = lr + p * 16;
            cpasync16(bb + r * 128 + ((lu ^ (r & 7)) << 4), Bg + (size_t)r * Kk + lu * 8);
        }
        asm volatile("cp.async.commit_group;" ::: "memory");
    };

    auto compute_stage = [&](int it) {
        const uint32_t ab = sbase + (it % STAGES) * STG_BYTES;
        const uint32_t bb = ab + A_BYTES;
        const int j  = lane >> 3;
        const int rr = lane & 7;
        #pragma unroll
        for (int ks = 0; ks < 4; ks++) {
            const int ub = ks * 2;
            uint32_t af[4][4];
            #pragma unroll
            for (int mf = 0; mf < 4; mf++) {
                const int row  = wm + mf * 16 + (j & 1) * 8 + rr;
                const int unit = ub + (j >> 1);
                ldmatrix_x4(af[mf][0], af[mf][1], af[mf][2], af[mf][3],
                            ab + row * 128 + ((unit ^ (row & 7)) << 4));
            }
            uint32_t bf[8][2];
            #pragma unroll
            for (int nb = 0; nb < 4; nb++) {
                const int row  = wn + nb * 16 + (j >> 1) * 8 + rr;
                const int unit = ub + (j & 1);
                uint32_t r0, r1, r2, r3;
                ldmatrix_x4(r0, r1, r2, r3, bb + row * 128 + ((unit ^ (row & 7)) << 4));
                bf[nb * 2 + 0][0] = r0; bf[nb * 2 + 0][1] = r1;
                bf[nb * 2 + 1][0] = r2; bf[nb * 2 + 1][1] = r3;
            }
            #pragma unroll
            for (int mf = 0; mf < 4; mf++)
                #pragma unroll
                for (int nf = 0; nf < 8; nf++)
                    mma_f16(acc[mf][nf], af[mf], bf[nf]);
        }
    };

    const int nk = Kk / BK;
    load_stage(0);
    load_stage(1);
    for (int it = 0; it < nk; it++) {
        if (it + 1 < nk) asm volatile("cp.async.wait_group 1;" ::: "memory");
        else             asm volatile("cp.async.wait_group 0;" ::: "memory");
        __syncthreads();
        if (it + 2 < nk) load_stage(it + 2);
        compute_stage(it);
    }

    const int g = lane >> 2, tg = lane & 3;
    #pragma unroll
    for (int mf = 0; mf < 4; mf++) {
        #pragma unroll
        for (int nf = 0; nf < 8; nf++) {
            const int col = bc * BN + wn + nf * 8 + tg * 2;
            #pragma unroll
            for (int h = 0; h < 2; h++) {
                const int row = br * BM + wm + mf * 16 + g + h * 8;
                const float2 d = *(const float2*)(Dm + (size_t)row * Nn + col);
                float c0 = acc[mf][nf][h * 2 + 0] * d.x;
                float c1 = acc[mf][nf][h * 2 + 1] * d.y;
                __half2 o = __floats2half2_rn(c0, c1);
                *(__half2*)(C + (size_t)row * Nn + col) = o;
            }
        }
    }
}

// ============================================================================
// gemm_h: general config (round-8 exact). 256 threads, 8 warps (2Mx4N),
// warp tile 64x32, block 128x128, BK=64, 3-stage cp.async, 2 CTAs/SM.
// EPI: 0 = +bias[col] (may be null), 1 = gelu(c+bias[col]), 3 = +bias[row],
//      4 = bias[col] then fused GroupNorm (gamma/beta), fp32 out
// ============================================================================
template<int EPI, typename OutT>
__global__ __launch_bounds__(256, 2)
void gemm_h(const __half* __restrict__ A, const __half* __restrict__ B,
            const float* __restrict__ bias,
            const float* __restrict__ gm, const float* __restrict__ bt,
            OutT* __restrict__ C, int M, int Nn, int Kk)
{
    constexpr int BM = 128, BN = 128, BK = 64, STAGES = 3;
    constexpr int A_BYTES = BM * BK * 2;
    constexpr int B_BYTES = BN * BK * 2;
    constexpr int STG_BYTES = A_BYTES + B_BYTES;  // 32768
    extern __shared__ char smem[];
    const uint32_t sbase = smem_u32(smem);

    const int t    = threadIdx.x;
    const int lane = t & 31;
    const int wid  = t >> 5;
    const int wm   = (wid & 1) * 64;              // 2 warps along M
    const int wn   = (wid >> 1) * 32;             // 4 warps along N
    const int br   = blockIdx.y;
    const int bc   = blockIdx.x;

    const int lr = t >> 3;                        // 0..31 (+32 per pass)
    const int lu = t & 7;

    float acc[4][4][4];
    #pragma unroll
    for (int i = 0; i < 4; i++)
        #pragma unroll
        for (int j = 0; j < 4; j++)
            #pragma unroll
            for (int q = 0; q < 4; q++) acc[i][j][q] = 0.f;

    auto load_stage = [&](int it) {
        const uint32_t ab = sbase + (it % STAGES) * STG_BYTES;
        const uint32_t bb = ab + A_BYTES;
        const __half* Ag = A + (size_t)(br * BM) * Kk + it * BK;
        const __half* Bg = B + (size_t)(bc * BN) * Kk + it * BK;
        #pragma unroll
        for (int p = 0; p < 4; p++) {
            const int r = lr + p * 32;
            cpasync16(ab + r * 128 + ((lu ^ (r & 7)) << 4), Ag + (size_t)r * Kk + lu * 8);
        }
        #pragma unroll
        for (int p = 0; p < 4; p++) {
            const int r = lr + p * 32;
            cpasync16(bb + r * 128 + ((lu ^ (r & 7)) << 4), Bg + (size_t)r * Kk + lu * 8);
        }
        asm volatile("cp.async.commit_group;" ::: "memory");
    };

    auto compute_stage = [&](int it) {
        const uint32_t ab = sbase + (it % STAGES) * STG_BYTES;
        const uint32_t bb = ab + A_BYTES;
        const int j  = lane >> 3;
        const int rr = lane & 7;
        #pragma unroll
        for (int ks = 0; ks < 4; ks++) {
            const int ub = ks * 2;
            uint32_t af[4][4];
            #pragma unroll
            for (int mf = 0; mf < 4; mf++) {
                const int row  = wm + mf * 16 + (j & 1) * 8 + rr;
                const int unit = ub + (j >> 1);
                ldmatrix_x4(af[mf][0], af[mf][1], af[mf][2], af[mf][3],
                            ab + row * 128 + ((unit ^ (row & 7)) << 4));
            }
            uint32_t bf[4][2];
            #pragma unroll
            for (int nb = 0; nb < 2; nb++) {
                const int row  = wn + nb * 16 + (j >> 1) * 8 + rr;
                const int unit = ub + (j & 1);
                uint32_t r0, r1, r2, r3;
                ldmatrix_x4(r0, r1, r2, r3, bb + row * 128 + ((unit ^ (row & 7)) << 4));
                bf[nb * 2 + 0][0] = r0; bf[nb * 2 + 0][1] = r1;
                bf[nb * 2 + 1][0] = r2; bf[nb * 2 + 1][1] = r3;
            }
            #pragma unroll
            for (int mf = 0; mf < 4; mf++)
                #pragma unroll
                for (int nf = 0; nf < 4; nf++)
                    mma_f16(acc[mf][nf], af[mf], bf[nf]);
        }
    };

    const int nk = Kk / BK;
    load_stage(0);
    load_stage(1);
    for (int it = 0; it < nk; it++) {
        if (it + 1 < nk) asm volatile("cp.async.wait_group 1;" ::: "memory");
        else             asm volatile("cp.async.wait_group 0;" ::: "memory");
        __syncthreads();
        if (it + 2 < nk) load_stage(it + 2);
        compute_stage(it);
    }

    const int g = lane >> 2, tg = lane & 3;

    if (EPI == 4) {
        // bias[col] + fused GroupNorm. Warp covers 32 cols == exactly one group.
        #pragma unroll
        for (int mf = 0; mf < 4; mf++) {
            #pragma unroll
            for (int h = 0; h < 2; h++) {
                const int row = br * BM + wm + mf * 16 + g + h * 8;
                float v[8];
                #pragma unroll
                for (int nf = 0; nf < 4; nf++) {
                    const int col = bc * BN + wn + nf * 8 + tg * 2;
                    v[nf * 2 + 0] = acc[mf][nf][h * 2 + 0] + bias[col];
                    v[nf * 2 + 1] = acc[mf][nf][h * 2 + 1] + bias[col + 1];
                }
                float s = 0.f, s2 = 0.f;
                #pragma unroll
                for (int q = 0; q < 8; q++) { s += v[q]; s2 += v[q] * v[q]; }
                s  += __shfl_xor_sync(0xffffffffu, s, 1);
                s  += __shfl_xor_sync(0xffffffffu, s, 2);
                s2 += __shfl_xor_sync(0xffffffffu, s2, 1);
                s2 += __shfl_xor_sync(0xffffffffu, s2, 2);
                const float mu  = s * (1.f / 32.f);
                const float var = s2 * (1.f / 32.f) - mu * mu;
                const float inv = rsqrtf(var + GN_EPS);
                #pragma unroll
                for (int nf = 0; nf < 4; nf++) {
                    const int col = bc * BN + wn + nf * 8 + tg * 2;
                    float c0 = (v[nf * 2 + 0] - mu) * inv * gm[col]     + bt[col];
                    float c1 = (v[nf * 2 + 1] - mu) * inv * gm[col + 1] + bt[col + 1];
                    float2 o = { c0, c1 };
                    *(float2*)((float*)C + (size_t)row * Nn + col) = o;
                }
            }
        }
        return;
    }

    #pragma unroll
    for (int mf = 0; mf < 4; mf++) {
        #pragma unroll
        for (int nf = 0; nf < 4; nf++) {
            const int col = bc * BN + wn + nf * 8 + tg * 2;
            #pragma unroll
            for (int h = 0; h < 2; h++) {
                const int row = br * BM + wm + mf * 16 + g + h * 8;
                float c0 = acc[mf][nf][h * 2 + 0];
                float c1 = acc[mf][nf][h * 2 + 1];
                if (EPI == 3) {
                    const float b = bias[row];
                    c0 += b; c1 += b;
                } else {
                    if (bias) { c0 += bias[col]; c1 += bias[col + 1]; }
                    if (EPI == 1) {
                        c0 = 0.5f * c0 * (1.f + erff(c0 * 0.70710678118654752f));
                        c1 = 0.5f * c1 * (1.f + erff(c1 * 0.70710678118654752f));
                    }
                }
                OutT* Cq = C + (size_t)row * Nn + col;
                __half2 o = __floats2half2_rn(c0, c1);
                *(__half2*)Cq = o;
            }
        }
    }
}

// ---------------- fused prep: 5 weight transposes (fp32->fp16) + x fp32->fp16 ----------------
__global__ void prep_k(const float* __restrict__ Wq, const float* __restrict__ Wk,
                       const float* __restrict__ Wv, const float* __restrict__ Wf,
                       const float* __restrict__ Wp, const float* __restrict__ x,
                       __half* __restrict__ Wt, __half* __restrict__ xh)
{
    const int b = blockIdx.x;
    const int t = threadIdx.x;
    if (b < 1280) {
        __shared__ float tile[32][33];
        const int w  = b >> 8;                   // weight index 0..4
        const int ti = b & 255;
        const int bx = ti & 15, by = ti >> 4;
        const float* in = (w == 0) ? Wq : (w == 1) ? Wk : (w == 2) ? Wv : (w == 3) ? Wf : Wp;
        __half* out = Wt + (size_t)w * DIM * DIM;
        const int tx = t & 31, tyb = t >> 5;     // 32 x 8
        int x0 = bx * 32 + tx;
        #pragma unroll
        for (int i = 0; i < 32; i += 8)
            tile[tyb + i][tx] = in[(size_t)(by * 32 + tyb + i) * DIM + x0];
        __syncthreads();
        int x1 = by * 32 + tx;
        #pragma unroll
        for (int i = 0; i < 32; i += 8)
            out[(size_t)(bx * 32 + tyb + i) * DIM + x1] = __float2half_rn(tile[tx][tyb + i]);
    } else {
        const int i = (b - 1280) * 256 + t;      // < 1048576
        float4 v = ((const float4*)x)[i];
        __half2 a = __floats2half2_rn(v.x, v.y);
        __half2 c = __floats2half2_rn(v.z, v.w);
        uint2 o = { *(uint32_t*)&a, *(uint32_t*)&c };
        ((uint2*)xh)[i] = o;
    }
}

// ---------------- launch ----------------
extern "C" void kernel_launch(void* const* d_in, const int* in_sizes, int n_in,
                              void* d_out, int out_size)
{
    const float* x     = (const float*)d_in[0];
    const float* D     = (const float*)d_in[1];
    const float* Wq    = (const float*)d_in[2];
    const float* bq    = (const float*)d_in[3];
    const float* Wk    = (const float*)d_in[4];
    const float* bk    = (const float*)d_in[5];
    const float* Wv    = (const float*)d_in[6];
    const float* bv    = (const float*)d_in[7];
    const float* Wf    = (const float*)d_in[8];
    const float* bf    = (const float*)d_in[9];
    const float* Wp    = (const float*)d_in[10];
    const float* bp    = (const float*)d_in[11];
    const float* gamma = (const float*)d_in[12];
    const float* beta  = (const float*)d_in[13];
    float* out = (float*)d_out;

    __half *Q, *K, *Vt, *S, *X, *H, *xh, *Wt;
    cudaGetSymbolAddress((void**)&Q,  g_Q);
    cudaGetSymbolAddress((void**)&K,  g_K);
    cudaGetSymbolAddress((void**)&Vt, g_Vt);
    cudaGetSymbolAddress((void**)&S,  g_S);
    cudaGetSymbolAddress((void**)&X,  g_X);
    cudaGetSymbolAddress((void**)&H,  g_H);
    cudaGetSymbolAddress((void**)&xh, g_xh);
    cudaGetSymbolAddress((void**)&Wt, g_Wt);

    __half* Wqt = Wt + 0 * (size_t)DIM * DIM;
    __half* Wkt = Wt + 1 * (size_t)DIM * DIM;
    __half* Wvt = Wt + 2 * (size_t)DIM * DIM;
    __half* Wft = Wt + 3 * (size_t)DIM * DIM;
    __half* Wpt = Wt + 4 * (size_t)DIM * DIM;

    const int SMEM = 3 * (128 + 128) * 64 * 2;   // 98304 B per CTA
    cudaFuncSetAttribute(gemm_w,            cudaFuncAttributeMaxDynamicSharedMemorySize, SMEM);
    cudaFuncSetAttribute(gemm_h<0, __half>, cudaFuncAttributeMaxDynamicSharedMemorySize, SMEM);
    cudaFuncSetAttribute(gemm_h<1, __half>, cudaFuncAttributeMaxDynamicSharedMemorySize, SMEM);
    cudaFuncSetAttribute(gemm_h<3, __half>, cudaFuncAttributeMaxDynamicSharedMemorySize, SMEM);
    cudaFuncSetAttribute(gemm_h<4, float>,  cudaFuncAttributeMaxDynamicSharedMemorySize, SMEM);

    dim3 blkH(256), blkW(128);
    dim3 g_thin(DIM / 128, N_TOK / 128);         // 4 x 64 = 256
    dim3 g_fat (N_TOK / 128, N_TOK / 128);       // 64 x 64 = 4096
    dim3 g_vt  (N_TOK / 128, DIM / 128);         // 64 x 4  = 256

    // 1. prep: weight transposes + x conversion
    prep_k<<<5376, 256>>>(Wq, Wk, Wv, Wf, Wp, x, Wt, xh);
    // 2. Vt[d][n] = Wv^T row d . x row n + bv[d]  (row-bias)
    gemm_h<3, __half><<<g_vt, blkH, SMEM>>>(Wvt, xh, bv, nullptr, nullptr,
                                            Vt, DIM, N_TOK, DIM);
    // 3-4. Q and K projections (separate launches — batching measured -28us regression)
    gemm_h<0, __half><<<g_thin, blkH, SMEM>>>(xh, Wqt, bq, nullptr, nullptr,
                                              Q, N_TOK, DIM, DIM);
    gemm_h<0, __half><<<g_thin, blkH, SMEM>>>(xh, Wkt, bk, nullptr, nullptr,
                                              K, N_TOK, DIM, DIM);
    // 5. S = fp16( D .* (Q @ K^T) )  -- gemm_w: measured 225.8us (best config)
    gemm_w<<<g_fat, blkW, SMEM>>>(Q, K, D, S, N_TOK, N_TOK, DIM);
    // 6. X = fp16( S @ V ) = S @ Vt^T  -- gemm_h (16 warps/SM hides DRAM streaming)
    gemm_h<0, __half><<<g_thin, blkH, SMEM>>>(S, Vt, nullptr, nullptr, nullptr,
                                              X, N_TOK, DIM, N_TOK);
    // 7. H = fp16( gelu(X @ Wf + bf) )
    gemm_h<1, __half><<<g_thin, blkH, SMEM>>>(X, Wft, bf, nullptr, nullptr,
                                              H, N_TOK, DIM, DIM);
    // 8. out = GroupNorm(H @ Wp + bp) fused
    gemm_h<4, float><<<g_thin, blkH, SMEM>>>(H, Wpt, bp, gamma, beta,
                                             out, N_TOK, DIM, DIM);
}

// round 15
// speedup vs baseline: 1.2226x; 1.0510x over previous
#include <cuda_runtime.h>
#include <cuda_fp16.h>
#include <math.h>
#include <stdint.h>

#define N_TOK 8192
#define DIM   512
#define GN_EPS 1e-5f

// ---------------- scratch (static device arrays; runtime alloc is forbidden) ----------------
__device__ __half g_Q [(size_t)N_TOK * DIM];
__device__ __half g_K [(size_t)N_TOK * DIM];
__device__ __half g_Vt[(size_t)N_TOK * DIM];         // V transposed [DIM][N_TOK]
__device__ __half g_S [(size_t)N_TOK * N_TOK];       // 128 MB retention matrix (fp16)
__device__ __half g_X [(size_t)N_TOK * DIM];
__device__ __half g_H [(size_t)N_TOK * DIM];
__device__ __half g_xh[(size_t)N_TOK * DIM];         // fp16 x
__device__ __half g_Wt[5 * (size_t)DIM * DIM];       // transposed fp16 weights

// ---------------- helpers ----------------
__device__ __forceinline__ uint32_t smem_u32(const void* p) {
    return (uint32_t)__cvta_generic_to_shared(p);
}
__device__ __forceinline__ void cpasync16(uint32_t dst, const void* src) {
    asm volatile("cp.async.cg.shared.global [%0], [%1], 16;" :: "r"(dst), "l"(src));
}
__device__ __forceinline__ void ldmatrix_x4(uint32_t& r0, uint32_t& r1, uint32_t& r2, uint32_t& r3,
                                            uint32_t addr) {
    asm volatile("ldmatrix.sync.aligned.m8n8.x4.shared.b16 {%0,%1,%2,%3}, [%4];"
                 : "=r"(r0), "=r"(r1), "=r"(r2), "=r"(r3) : "r"(addr));
}
__device__ __forceinline__ void mma_f16(float* c, const uint32_t* a, const uint32_t* b) {
    asm volatile("mma.sync.aligned.m16n8k16.row.col.f32.f16.f16.f32 "
                 "{%0,%1,%2,%3}, {%4,%5,%6,%7}, {%8,%9}, {%0,%1,%2,%3};"
                 : "+f"(c[0]), "+f"(c[1]), "+f"(c[2]), "+f"(c[3])
                 : "r"(a[0]), "r"(a[1]), "r"(a[2]), "r"(a[3]), "r"(b[0]), "r"(b[1]));
}

// ---------------- fp16 NT tensor-core GEMM (round-8 exact) ----------------
// C[M,Nn] = A[M,Kk] @ B^T, A/B are __half [.][Kk] row-major, fp32 accumulate.
// Block 128x128, 8 warps (2 M x 4 N), warp tile 64x32, BK=64 (128B rows, SW128 swizzle),
// 3-stage cp.async pipeline, 2 CTAs/SM.
// EPI: 0 = +bias[col] (may be null), 1 = gelu(c+bias[col]), 2 = c * Dm[row,col],
//      3 = +bias[row], 4 = bias[col] then fused GroupNorm (gamma/beta), fp32 out
template<int EPI, typename OutT>
__global__ __launch_bounds__(256, 2)
void gemm_h(const __half* __restrict__ A, const __half* __restrict__ B,
            const float* __restrict__ bias, const float* __restrict__ Dm,
            const float* __restrict__ gm, const float* __restrict__ bt,
            OutT* __restrict__ C, int M, int Nn, int Kk)
{
    constexpr int BM = 128, BN = 128, BK = 64, STAGES = 3;
    constexpr int A_BYTES = BM * BK * 2;          // 16384
    constexpr int B_BYTES = BN * BK * 2;          // 16384
    constexpr int STG_BYTES = A_BYTES + B_BYTES;  // 32768
    extern __shared__ char smem[];
    const uint32_t sbase = smem_u32(smem);

    const int t    = threadIdx.x;
    const int lane = t & 31;
    const int wid  = t >> 5;
    const int wm   = (wid & 1) * 64;              // 2 warps along M
    const int wn   = (wid >> 1) * 32;             // 4 warps along N
    const int br   = blockIdx.y;
    const int bc   = blockIdx.x;

    const int lr = t >> 3;                        // 0..31 (+32 per pass)
    const int lu = t & 7;                         // 16B unit in 128B row

    float acc[4][4][4];
    #pragma unroll
    for (int i = 0; i < 4; i++)
        #pragma unroll
        for (int j = 0; j < 4; j++)
            #pragma unroll
            for (int q = 0; q < 4; q++) acc[i][j][q] = 0.f;

    auto load_stage = [&](int it) {
        const uint32_t ab = sbase + (it % STAGES) * STG_BYTES;
        const uint32_t bb = ab + A_BYTES;
        const __half* Ag = A + (size_t)(br * BM) * Kk + it * BK;
        const __half* Bg = B + (size_t)(bc * BN) * Kk + it * BK;
        #pragma unroll
        for (int p = 0; p < 4; p++) {
            const int r = lr + p * 32;
            cpasync16(ab + r * 128 + ((lu ^ (r & 7)) << 4), Ag + (size_t)r * Kk + lu * 8);
        }
        #pragma unroll
        for (int p = 0; p < 4; p++) {
            const int r = lr + p * 32;
            cpasync16(bb + r * 128 + ((lu ^ (r & 7)) << 4), Bg + (size_t)r * Kk + lu * 8);
        }
        asm volatile("cp.async.commit_group;" ::: "memory");
    };

    auto compute_stage = [&](int it) {
        const uint32_t ab = sbase + (it % STAGES) * STG_BYTES;
        const uint32_t bb = ab + A_BYTES;
        const int j  = lane >> 3;
        const int rr = lane & 7;
        #pragma unroll
        for (int ks = 0; ks < 4; ks++) {
            const int ub = ks * 2;
            uint32_t af[4][4];
            #pragma unroll
            for (int mf = 0; mf < 4; mf++) {
                const int row  = wm + mf * 16 + (j & 1) * 8 + rr;
                const int unit = ub + (j >> 1);
                ldmatrix_x4(af[mf][0], af[mf][1], af[mf][2], af[mf][3],
                            ab + row * 128 + ((unit ^ (row & 7)) << 4));
            }
            uint32_t bf[4][2];
            #pragma unroll
            for (int nb = 0; nb < 2; nb++) {
                const int row  = wn + nb * 16 + (j >> 1) * 8 + rr;
                const int unit = ub + (j & 1);
                uint32_t r0, r1, r2, r3;
                ldmatrix_x4(r0, r1, r2, r3, bb + row * 128 + ((unit ^ (row & 7)) << 4));
                bf[nb * 2 + 0][0] = r0; bf[nb * 2 + 0][1] = r1;
                bf[nb * 2 + 1][0] = r2; bf[nb * 2 + 1][1] = r3;
            }
            #pragma unroll
            for (int mf = 0; mf < 4; mf++)
                #pragma unroll
                for (int nf = 0; nf < 4; nf++)
                    mma_f16(acc[mf][nf], af[mf], bf[nf]);
        }
    };

    const int nk = Kk / BK;
    load_stage(0);
    load_stage(1);
    for (int it = 0; it < nk; it++) {
        if (it + 1 < nk) asm volatile("cp.async.wait_group 1;" ::: "memory");
        else             asm volatile("cp.async.wait_group 0;" ::: "memory");
        __syncthreads();
        if (it + 2 < nk) load_stage(it + 2);
        compute_stage(it);
    }

    // ---- epilogue ----
    const int g = lane >> 2, tg = lane & 3;

    if (EPI == 4) {
        // bias[col] + fused GroupNorm. Warp covers 32 cols == exactly one group.
        #pragma unroll
        for (int mf = 0; mf < 4; mf++) {
            #pragma unroll
            for (int h = 0; h < 2; h++) {
                const int row = br * BM + wm + mf * 16 + g + h * 8;
                float v[8];
                #pragma unroll
                for (int nf = 0; nf < 4; nf++) {
                    const int col = bc * BN + wn + nf * 8 + tg * 2;
                    v[nf * 2 + 0] = acc[mf][nf][h * 2 + 0] + bias[col];
                    v[nf * 2 + 1] = acc[mf][nf][h * 2 + 1] + bias[col + 1];
                }
                float s = 0.f, s2 = 0.f;
                #pragma unroll
                for (int q = 0; q < 8; q++) { s += v[q]; s2 += v[q] * v[q]; }
                s  += __shfl_xor_sync(0xffffffffu, s, 1);
                s  += __shfl_xor_sync(0xffffffffu, s, 2);
                s2 += __shfl_xor_sync(0xffffffffu, s2, 1);
                s2 += __shfl_xor_sync(0xffffffffu, s2, 2);
                const float mu  = s * (1.f / 32.f);
                const float var = s2 * (1.f / 32.f) - mu * mu;
                const float inv = rsqrtf(var + GN_EPS);
                #pragma unroll
                for (int nf = 0; nf < 4; nf++) {
                    const int col = bc * BN + wn + nf * 8 + tg * 2;
                    float c0 = (v[nf * 2 + 0] - mu) * inv * gm[col]     + bt[col];
                    float c1 = (v[nf * 2 + 1] - mu) * inv * gm[col + 1] + bt[col + 1];
                    float2 o = { c0, c1 };
                    *(float2*)((float*)C + (size_t)row * Nn + col) = o;
                }
            }
        }
        return;
    }

    #pragma unroll
    for (int mf = 0; mf < 4; mf++) {
        #pragma unroll
        for (int nf = 0; nf < 4; nf++) {
            const int col = bc * BN + wn + nf * 8 + tg * 2;
            #pragma unroll
            for (int h = 0; h < 2; h++) {
                const int row = br * BM + wm + mf * 16 + g + h * 8;
                float c0 = acc[mf][nf][h * 2 + 0];
                float c1 = acc[mf][nf][h * 2 + 1];
                if (EPI == 2) {
                    const float2 d = *(const float2*)(Dm + (size_t)row * Nn + col);
                    c0 *= d.x; c1 *= d.y;
                } else if (EPI == 3) {
                    const float b = bias[row];
                    c0 += b; c1 += b;
                } else {
                    if (bias) { c0 += bias[col]; c1 += bias[col + 1]; }
                    if (EPI == 1) {
                        c0 = 0.5f * c0 * (1.f + erff(c0 * 0.70710678118654752f));
                        c1 = 0.5f * c1 * (1.f + erff(c1 * 0.70710678118654752f));
                    }
                }
                OutT* Cp = C + (size_t)row * Nn + col;
                if (sizeof(OutT) == 2) {
                    __half2 o = __floats2half2_rn(c0, c1);
                    *(__half2*)Cp = o;
                } else {
                    float2 o = { c0, c1 };
                    *(float2*)Cp = o;
                }
            }
        }
    }
}

// ---------------- fused prep: 5 weight transposes (fp32->fp16) + x fp32->fp16 ----------------
__global__ void prep_k(const float* __restrict__ Wq, const float* __restrict__ Wk,
                       const float* __restrict__ Wv, const float* __restrict__ Wf,
                       const float* __restrict__ Wp, const float* __restrict__ x,
                       __half* __restrict__ Wt, __half* __restrict__ xh)
{
    const int b = blockIdx.x;
    const int t = threadIdx.x;
    if (b < 1280) {
        __shared__ float tile[32][33];
        const int w  = b >> 8;                   // weight index 0..4
        const int ti = b & 255;
        const int bx = ti & 15, by = ti >> 4;
        const float* in = (w == 0) ? Wq : (w == 1) ? Wk : (w == 2) ? Wv : (w == 3) ? Wf : Wp;
        __half* out = Wt + (size_t)w * DIM * DIM;
        const int tx = t & 31, tyb = t >> 5;     // 32 x 8
        int x0 = bx * 32 + tx;
        #pragma unroll
        for (int i = 0; i < 32; i += 8)
            tile[tyb + i][tx] = in[(size_t)(by * 32 + tyb + i) * DIM + x0];
        __syncthreads();
        int x1 = by * 32 + tx;
        #pragma unroll
        for (int i = 0; i < 32; i += 8)
            out[(size_t)(bx * 32 + tyb + i) * DIM + x1] = __float2half_rn(tile[tx][tyb + i]);
    } else {
        const int i = (b - 1280) * 256 + t;      // < 1048576
        float4 v = ((const float4*)x)[i];
        __half2 a = __floats2half2_rn(v.x, v.y);
        __half2 c = __floats2half2_rn(v.z, v.w);
        uint2 o = { *(uint32_t*)&a, *(uint32_t*)&c };
        ((uint2*)xh)[i] = o;
    }
}

// ---------------- streams/events for intra-graph parallelism (host objects, lazy-init) ----
static cudaStream_t g_s1 = nullptr;   // K projection branch
static cudaStream_t g_s2 = nullptr;   // Vt branch
static cudaEvent_t  g_e0 = nullptr;   // prep done
static cudaEvent_t  g_e1 = nullptr;   // K done
static cudaEvent_t  g_e2 = nullptr;   // Vt done

// ---------------- launch ----------------
extern "C" void kernel_launch(void* const* d_in, const int* in_sizes, int n_in,
                              void* d_out, int out_size)
{
    const float* x     = (const float*)d_in[0];
    const float* D     = (const float*)d_in[1];
    const float* Wq    = (const float*)d_in[2];
    const float* bq    = (const float*)d_in[3];
    const float* Wk    = (const float*)d_in[4];
    const float* bk    = (const float*)d_in[5];
    const float* Wv    = (const float*)d_in[6];
    const float* bv    = (const float*)d_in[7];
    const float* Wf    = (const float*)d_in[8];
    const float* bf    = (const float*)d_in[9];
    const float* Wp    = (const float*)d_in[10];
    const float* bp    = (const float*)d_in[11];
    const float* gamma = (const float*)d_in[12];
    const float* beta  = (const float*)d_in[13];
    float* out = (float*)d_out;

    if (!g_s1) {
        cudaStreamCreateWithFlags(&g_s1, cudaStreamNonBlocking);
        cudaStreamCreateWithFlags(&g_s2, cudaStreamNonBlocking);
        cudaEventCreateWithFlags(&g_e0, cudaEventDisableTiming);
        cudaEventCreateWithFlags(&g_e1, cudaEventDisableTiming);
        cudaEventCreateWithFlags(&g_e2, cudaEventDisableTiming);
    }

    __half *Q, *K, *Vt, *S, *X, *H, *xh, *Wt;
    cudaGetSymbolAddress((void**)&Q,  g_Q);
    cudaGetSymbolAddress((void**)&K,  g_K);
    cudaGetSymbolAddress((void**)&Vt, g_Vt);
    cudaGetSymbolAddress((void**)&S,  g_S);
    cudaGetSymbolAddress((void**)&X,  g_X);
    cudaGetSymbolAddress((void**)&H,  g_H);
    cudaGetSymbolAddress((void**)&xh, g_xh);
    cudaGetSymbolAddress((void**)&Wt, g_Wt);

    __half* Wqt = Wt + 0 * (size_t)DIM * DIM;
    __half* Wkt = Wt + 1 * (size_t)DIM * DIM;
    __half* Wvt = Wt + 2 * (size_t)DIM * DIM;
    __half* Wft = Wt + 3 * (size_t)DIM * DIM;
    __half* Wpt = Wt + 4 * (size_t)DIM * DIM;

    const int SMEM = 3 * (128 + 128) * 64 * 2;   // 98304 B per CTA
    cudaFuncSetAttribute(gemm_h<0, __half>, cudaFuncAttributeMaxDynamicSharedMemorySize, SMEM);
    cudaFuncSetAttribute(gemm_h<1, __half>, cudaFuncAttributeMaxDynamicSharedMemorySize, SMEM);
    cudaFuncSetAttribute(gemm_h<2, __half>, cudaFuncAttributeMaxDynamicSharedMemorySize, SMEM);
    cudaFuncSetAttribute(gemm_h<3, __half>, cudaFuncAttributeMaxDynamicSharedMemorySize, SMEM);
    cudaFuncSetAttribute(gemm_h<4, float>,  cudaFuncAttributeMaxDynamicSharedMemorySize, SMEM);

    dim3 blk(256);
    dim3 g_thin(DIM / 128, N_TOK / 128);     // 4 x 64 = 256
    dim3 g_fat (N_TOK / 128, N_TOK / 128);   // 64 x 64 = 4096
    dim3 g_vt  (N_TOK / 128, DIM / 128);     // 64 x 4  = 256

    // 1. prep on legacy stream; fork side branches afterwards
    prep_k<<<5376, 256>>>(Wq, Wk, Wv, Wf, Wp, x, Wt, xh);
    cudaEventRecord(g_e0, 0);
    cudaStreamWaitEvent(g_s1, g_e0, 0);
    cudaStreamWaitEvent(g_s2, g_e0, 0);

    // 2a. Q projection (legacy stream)
    gemm_h<0, __half><<<g_thin, blk, SMEM>>>(xh, Wqt, bq, nullptr, nullptr, nullptr,
                                             Q, N_TOK, DIM, DIM);
    // 2b. K projection (stream 1 — concurrent with Q)
    gemm_h<0, __half><<<g_thin, blk, SMEM, g_s1>>>(xh, Wkt, bk, nullptr, nullptr, nullptr,
                                                   K, N_TOK, DIM, DIM);
    // 2c. Vt (stream 2 — hidden under Q/K/QK^T; joined only before S@V)
    gemm_h<3, __half><<<g_vt, blk, SMEM, g_s2>>>(Wvt, xh, bv, nullptr, nullptr, nullptr,
                                                 Vt, DIM, N_TOK, DIM);

    // join K before QK^T
    cudaEventRecord(g_e1, g_s1);
    cudaStreamWaitEvent(0, g_e1, 0);
    // 3. S = fp16( D .* (Q @ K^T) )
    gemm_h<2, __half><<<g_fat, blk, SMEM>>>(Q, K, nullptr, D, nullptr, nullptr,
                                            S, N_TOK, N_TOK, DIM);

    // join Vt before S@V
    cudaEventRecord(g_e2, g_s2);
    cudaStreamWaitEvent(0, g_e2, 0);
    // 4. X = fp16( S @ V ) = S @ Vt^T
    gemm_h<0, __half><<<g_thin, blk, SMEM>>>(S, Vt, nullptr, nullptr, nullptr, nullptr,
                                             X, N_TOK, DIM, N_TOK);
    // 5. H = fp16( gelu(X @ Wf + bf) )
    gemm_h<1, __half><<<g_thin, blk, SMEM>>>(X, Wft, bf, nullptr, nullptr, nullptr,
                                             H, N_TOK, DIM, DIM);
    // 6. out = GroupNorm(H @ Wp + bp) fused
    gemm_h<4, float><<<g_thin, blk, SMEM>>>(H, Wpt, bp, nullptr, gamma, beta,
                                            out, N_TOK, DIM, DIM);
}